// round 4
// baseline (speedup 1.0000x reference)
#include <cuda_runtime.h>
#include <math.h>

#define NNODES 100000
#define FIN    512
#define HID    256
#define NC     40
#define KSTEPS 10
#define EMAX   3200000
#define ALPHA  0.1f

// ---------------- device scratch (no allocations allowed) ----------------
__device__ float g_hid[NNODES * HID];      // ~102 MB
__device__ float g_h  [NNODES * NC];       // 16 MB
__device__ float g_zA [NNODES * NC];
__device__ float g_zB [NNODES * NC];
__device__ float g_dinv[NNODES];
__device__ int   g_deg [NNODES];
__device__ int   g_rowptr[NNODES + 1];
__device__ int   g_fill[NNODES];
__device__ int   g_colidx[EMAX];
__device__ float g_ew   [EMAX];

// ---------------- packed f32x2 helpers (sm_103a FFMA2 via PTX) ----------------
__device__ __forceinline__ void fma2(unsigned long long &d, unsigned long long a,
                                     unsigned long long b) {
    asm("fma.rn.f32x2 %0, %1, %2, %3;" : "=l"(d) : "l"(a), "l"(b), "l"(d));
}
__device__ __forceinline__ unsigned long long pack2(float v) {
    unsigned long long r;
    unsigned int u = __float_as_uint(v);
    asm("mov.b64 %0, {%1, %2};" : "=l"(r) : "r"(u), "r"(u));
    return r;
}
__device__ __forceinline__ float2 unpack2(unsigned long long p) {
    unsigned int lo, hi;
    asm("mov.b64 {%0, %1}, %2;" : "=r"(lo), "=r"(hi) : "l"(p));
    return make_float2(__uint_as_float(lo), __uint_as_float(hi));
}

// ---------------- graph preprocessing ----------------
__global__ void zero_deg_kernel() {
    int i = blockIdx.x * blockDim.x + threadIdx.x;
    if (i < NNODES) g_deg[i] = 0;
}

__global__ void count_deg_kernel(const int* __restrict__ ei, int E) {
    int e = blockIdx.x * blockDim.x + threadIdx.x;
    if (e < E) atomicAdd(&g_deg[ei[e]], 1);
}

// single-block exclusive scan over g_deg -> g_rowptr, also dinv + fill init
__global__ void scan_kernel(int E) {
    const int T = 1024;
    const int CH = (NNODES + T - 1) / T;
    int t = threadIdx.x;
    int beg = t * CH;
    int end = beg + CH; if (end > NNODES) end = NNODES;
    if (beg > NNODES) beg = NNODES;

    int sum = 0;
    for (int i = beg; i < end; i++) sum += g_deg[i];

    __shared__ int sh[1024];
    sh[t] = sum;
    __syncthreads();
    for (int off = 1; off < T; off <<= 1) {
        int v = (t >= off) ? sh[t - off] : 0;
        __syncthreads();
        sh[t] += v;
        __syncthreads();
    }
    int offset = sh[t] - sum;

    int running = offset;
    for (int i = beg; i < end; i++) {
        g_rowptr[i] = running;
        g_fill[i]   = running;
        g_dinv[i]   = rsqrtf((float)(g_deg[i] + 1));   // +1 self-loop
        running += g_deg[i];
    }
    if (t == T - 1) g_rowptr[NNODES] = sh[T - 1];
}

__global__ void scatter_kernel(const int* __restrict__ ei, int E) {
    int e = blockIdx.x * blockDim.x + threadIdx.x;
    if (e >= E) return;
    int r = ei[e];          // destination
    int c = ei[E + e];      // source
    int pos = atomicAdd(&g_fill[r], 1);
    g_colidx[pos] = c;
    g_ew[pos] = g_dinv[r] * g_dinv[c];
}

// ---------------- GEMM1: h1 = relu(x @ W1 + b1)  [100000,512]x[512,256] ----------------
// BM=128 BN=128 BK=16, 256 threads, thread tile 8x8 via f32x2, double-buffered smem
__global__ __launch_bounds__(256, 2) void gemm1_kernel(
    const float* __restrict__ X, const float* __restrict__ W1, const float* __restrict__ b1)
{
    __shared__ __align__(16) float As[2][16][132];   // [k][m]
    __shared__ __align__(16) float Bs[2][16][132];   // [k][n]

    const int tid = threadIdx.x;
    const int m0 = blockIdx.x * 128;
    const int n0 = blockIdx.y * 128;

    const int tx = tid & 15;       // n: 16 groups x 8 cols
    const int ty = tid >> 4;       // m: 16 groups x 8 rows

    unsigned long long acc[8][4];
    #pragma unroll
    for (int i = 0; i < 8; i++)
        #pragma unroll
        for (int p = 0; p < 4; p++) acc[i][p] = 0ULL;

    float4 ar[2], br[2];

    // prologue: tile 0
    {
        #pragma unroll
        for (int l = 0; l < 2; l++) {
            int q = tid + l * 256;
            int m = q >> 2, kq = q & 3;
            int row = m0 + m; if (row > NNODES - 1) row = NNODES - 1;
            ar[l] = *(const float4*)&X[(size_t)row * FIN + kq * 4];
        }
        #pragma unroll
        for (int l = 0; l < 2; l++) {
            int q = tid + l * 256;
            int kr = q >> 5, nq = q & 31;
            br[l] = *(const float4*)&W1[(size_t)kr * HID + n0 + nq * 4];
        }
        #pragma unroll
        for (int l = 0; l < 2; l++) {
            int q = tid + l * 256;
            int m = q >> 2, kq = q & 3;
            float4 v = ar[l];
            As[0][kq * 4 + 0][m] = v.x;
            As[0][kq * 4 + 1][m] = v.y;
            As[0][kq * 4 + 2][m] = v.z;
            As[0][kq * 4 + 3][m] = v.w;
        }
        #pragma unroll
        for (int l = 0; l < 2; l++) {
            int q = tid + l * 256;
            int kr = q >> 5, nq = q & 31;
            *(float4*)&Bs[0][kr][nq * 4] = br[l];
        }
    }
    __syncthreads();

    const int TILES = FIN / 16;   // 32
    for (int t = 0; t < TILES; t++) {
        int buf = t & 1;

        if (t + 1 < TILES) {
            int k0 = (t + 1) * 16;
            #pragma unroll
            for (int l = 0; l < 2; l++) {
                int q = tid + l * 256;
                int m = q >> 2, kq = q & 3;
                int row = m0 + m; if (row > NNODES - 1) row = NNODES - 1;
                ar[l] = *(const float4*)&X[(size_t)row * FIN + k0 + kq * 4];
            }
            #pragma unroll
            for (int l = 0; l < 2; l++) {
                int q = tid + l * 256;
                int kr = q >> 5, nq = q & 31;
                br[l] = *(const float4*)&W1[(size_t)(k0 + kr) * HID + n0 + nq * 4];
            }
        }

        #pragma unroll
        for (int k = 0; k < 16; k++) {
            float4 a0 = *(float4*)&As[buf][k][ty * 8];
            float4 a1 = *(float4*)&As[buf][k][ty * 8 + 4];
            unsigned long long bb[4];
            {
                ulonglong2 b0 = *(ulonglong2*)&Bs[buf][k][tx * 8];
                ulonglong2 b1 = *(ulonglong2*)&Bs[buf][k][tx * 8 + 4];
                bb[0] = b0.x; bb[1] = b0.y; bb[2] = b1.x; bb[3] = b1.y;
            }
            float av[8] = {a0.x, a0.y, a0.z, a0.w, a1.x, a1.y, a1.z, a1.w};
            #pragma unroll
            for (int i = 0; i < 8; i++) {
                unsigned long long aa = pack2(av[i]);
                #pragma unroll
                for (int p = 0; p < 4; p++) fma2(acc[i][p], aa, bb[p]);
            }
        }

        if (t + 1 < TILES) {
            int nb = buf ^ 1;
            #pragma unroll
            for (int l = 0; l < 2; l++) {
                int q = tid + l * 256;
                int m = q >> 2, kq = q & 3;
                float4 v = ar[l];
                As[nb][kq * 4 + 0][m] = v.x;
                As[nb][kq * 4 + 1][m] = v.y;
                As[nb][kq * 4 + 2][m] = v.z;
                As[nb][kq * 4 + 3][m] = v.w;
            }
            #pragma unroll
            for (int l = 0; l < 2; l++) {
                int q = tid + l * 256;
                int kr = q >> 5, nq = q & 31;
                *(float4*)&Bs[nb][kr][nq * 4] = br[l];
            }
        }
        __syncthreads();
    }

    float bias[8];
    #pragma unroll
    for (int j = 0; j < 8; j++) bias[j] = b1[n0 + tx * 8 + j];

    #pragma unroll
    for (int i = 0; i < 8; i++) {
        int m = m0 + ty * 8 + i;
        if (m < NNODES) {
            float o[8];
            #pragma unroll
            for (int p = 0; p < 4; p++) {
                float2 v = unpack2(acc[i][p]);
                o[p * 2]     = fmaxf(v.x + bias[p * 2], 0.0f);
                o[p * 2 + 1] = fmaxf(v.y + bias[p * 2 + 1], 0.0f);
            }
            float* dst = &g_hid[(size_t)m * HID + n0 + tx * 8];
            *(float4*)dst       = make_float4(o[0], o[1], o[2], o[3]);
            *(float4*)(dst + 4) = make_float4(o[4], o[5], o[6], o[7]);
        }
    }
}

// ---------------- GEMM2: h = hid @ W2 + b2  [100000,256]x[256,40] ----------------
// BM=128 BK=32, 256 threads, thread tile 2 rows x 10 cols (5 f32x2 pairs)
__global__ __launch_bounds__(256) void gemm2_kernel(
    const float* __restrict__ W2, const float* __restrict__ b2)
{
    __shared__ __align__(8) float Hs[32][133];
    __shared__ __align__(8) float Ws[32][40];

    const int tid = threadIdx.x;
    const int m0 = blockIdx.x * 128;
    const int tx = tid & 3;        // 4 groups x 10 cols = 40
    const int ty = tid >> 2;       // 64 groups x 2 rows = 128

    unsigned long long acc0[5], acc1[5];
    #pragma unroll
    for (int j = 0; j < 5; j++) { acc0[j] = 0ULL; acc1[j] = 0ULL; }

    for (int k0 = 0; k0 < HID; k0 += 32) {
        {
            int kk = tid & 31;
            int mb = tid >> 5;     // 0..7
            #pragma unroll
            for (int mi = 0; mi < 16; mi++) {
                int m = mi * 8 + mb;
                int row = m0 + m; if (row > NNODES - 1) row = NNODES - 1;
                Hs[kk][m] = g_hid[(size_t)row * HID + k0 + kk];
            }
        }
        #pragma unroll
        for (int l = 0; l < 5; l++) {
            int idx = tid + l * 256;
            int kr = idx / 40;
            int n = idx - kr * 40;
            Ws[kr][n] = W2[(size_t)(k0 + kr) * NC + n];
        }
        __syncthreads();

        #pragma unroll
        for (int k = 0; k < 32; k++) {
            unsigned long long aa0 = pack2(Hs[k][ty * 2]);
            unsigned long long aa1 = pack2(Hs[k][ty * 2 + 1]);
            #pragma unroll
            for (int j = 0; j < 5; j++) {
                unsigned long long bb = *(unsigned long long*)&Ws[k][tx * 10 + 2 * j];
                fma2(acc0[j], aa0, bb);
                fma2(acc1[j], aa1, bb);
            }
        }
        __syncthreads();
    }

    #pragma unroll
    for (int r = 0; r < 2; r++) {
        int m = m0 + ty * 2 + r;
        if (m < NNODES) {
            float* dst = &g_h[(size_t)m * NC];
            #pragma unroll
            for (int j = 0; j < 5; j++) {
                int n = tx * 10 + 2 * j;
                float2 v = unpack2(r == 0 ? acc0[j] : acc1[j]);
                dst[n]     = v.x + b2[n];
                dst[n + 1] = v.y + b2[n + 1];
            }
        }
    }
}

// ---------------- APPNP propagation step: zout = 0.9*A_norm*zin + 0.1*h ----------------
// warp per row, lane c handles channels c and (c+32 if c<8)
// colidx/ew are use-once streams -> __ldcs (evict-first) keeps z resident in L2
__global__ __launch_bounds__(256) void spmm_kernel(int srcSel, int dstSel) {
    const float* zin  = (srcSel == 0) ? g_h : (srcSel == 1 ? g_zA : g_zB);
    float*       zout = (dstSel == 1) ? g_zA : g_zB;

    int w = (blockIdx.x * blockDim.x + threadIdx.x) >> 5;
    int lane = threadIdx.x & 31;
    if (w >= NNODES) return;
    int r = w;
    int s = g_rowptr[r];
    int e = g_rowptr[r + 1];

    float acc0 = 0.0f, acc1 = 0.0f;
    #pragma unroll 4
    for (int j = s; j < e; j++) {
        float wt = __ldcs(&g_ew[j]);
        int ci = __ldcs(&g_colidx[j]);
        const float* zb = zin + (size_t)ci * NC;
        acc0 += wt * zb[lane];
        if (lane < 8) acc1 += wt * zb[32 + lane];
    }
    // self loop
    float dv = g_dinv[r];
    float ws = dv * dv;
    const float* zr = zin + (size_t)r * NC;
    acc0 += ws * zr[lane];
    if (lane < 8) acc1 += ws * zr[32 + lane];

    const float* hr = g_h + (size_t)r * NC;
    float* zo = zout + (size_t)r * NC;
    zo[lane] = (1.0f - ALPHA) * acc0 + ALPHA * hr[lane];
    if (lane < 8) zo[32 + lane] = (1.0f - ALPHA) * acc1 + ALPHA * hr[32 + lane];
}

// ---------------- log_softmax over 40 classes, warp per row ----------------
__global__ __launch_bounds__(256) void logsoftmax_kernel(float* __restrict__ out) {
    int w = (blockIdx.x * blockDim.x + threadIdx.x) >> 5;
    int lane = threadIdx.x & 31;
    if (w >= NNODES) return;

    const float* zr = g_zB + (size_t)w * NC;
    float v0 = zr[lane];
    float v1 = (lane < 8) ? zr[32 + lane] : -3.4e38f;

    float m = fmaxf(v0, v1);
    #pragma unroll
    for (int off = 16; off > 0; off >>= 1)
        m = fmaxf(m, __shfl_xor_sync(0xffffffff, m, off));

    float s = __expf(v0 - m) + ((lane < 8) ? __expf(v1 - m) : 0.0f);
    #pragma unroll
    for (int off = 16; off > 0; off >>= 1)
        s += __shfl_xor_sync(0xffffffff, s, off);

    float lse = m + logf(s);
    float* o = out + (size_t)w * NC;
    o[lane] = v0 - lse;
    if (lane < 8) o[32 + lane] = v1 - lse;
}

// ---------------- launch ----------------
extern "C" void kernel_launch(void* const* d_in, const int* in_sizes, int n_in,
                              void* d_out, int out_size) {
    const float* x  = (const float*)d_in[0];
    const float* W1 = (const float*)d_in[1];
    const float* b1 = (const float*)d_in[2];
    const float* W2 = (const float*)d_in[3];
    const float* b2 = (const float*)d_in[4];
    const int*   ei = (const int*)d_in[5];
    float* out = (float*)d_out;
    int E = in_sizes[5] / 2;

    // graph preprocessing -> CSR + normalized weights
    zero_deg_kernel<<<(NNODES + 255) / 256, 256>>>();
    count_deg_kernel<<<(E + 255) / 256, 256>>>(ei, E);
    scan_kernel<<<1, 1024>>>(E);
    scatter_kernel<<<(E + 255) / 256, 256>>>(ei, E);

    // MLP encoder
    dim3 g1((NNODES + 127) / 128, HID / 128);
    gemm1_kernel<<<g1, 256>>>(x, W1, b1);
    gemm2_kernel<<<(NNODES + 127) / 128, 256>>>(W2, b2);

    // K=10 APPNP steps; src: 0=h 1=zA 2=zB, dst: 1=zA 2=zB
    int spmmGrid = (NNODES * 32 + 255) / 256;
    for (int i = 1; i <= KSTEPS; i++) {
        int src = (i == 1) ? 0 : ((i & 1) ? 2 : 1);
        int dst = (i & 1) ? 1 : 2;
        spmm_kernel<<<spmmGrid, 256>>>(src, dst);
    }

    // final z is in g_zB (K even)
    logsoftmax_kernel<<<spmmGrid, 256>>>(out);
}

// round 5
// speedup vs baseline: 1.3165x; 1.3165x over previous
#include <cuda_runtime.h>
#include <cuda_bf16.h>
#include <math.h>

#define NNODES 100000
#define FIN    512
#define HID    256
#define NC     40
#define KSTEPS 10
#define EMAX   3200000
#define ALPHA  0.1f

// ---------------- device scratch (no allocations allowed) ----------------
__device__ float g_hid[NNODES * HID];      // ~102 MB
__device__ float g_h  [NNODES * NC];       // 16 MB
__device__ float g_zA [NNODES * NC];
__device__ float g_zB [NNODES * NC];
__device__ float g_dinv[NNODES];
__device__ int   g_deg [NNODES];
__device__ int   g_rowptr[NNODES + 1];
__device__ int   g_fill[NNODES];
__device__ int   g_colidx[EMAX];
__device__ float g_ew   [EMAX];

// bf16 split operands for tensor-core gemm1
__device__ __nv_bfloat16 g_ah [NNODES * FIN];   // 102 MB
__device__ __nv_bfloat16 g_al [NNODES * FIN];   // 102 MB
__device__ __nv_bfloat16 g_whT[HID * FIN];      // [n][k] 0.26 MB
__device__ __nv_bfloat16 g_wlT[HID * FIN];

// ---------------- graph preprocessing ----------------
__global__ void zero_deg_kernel() {
    int i = blockIdx.x * blockDim.x + threadIdx.x;
    if (i < NNODES) g_deg[i] = 0;
}

__global__ void count_deg_kernel(const int* __restrict__ ei, int E) {
    int e = blockIdx.x * blockDim.x + threadIdx.x;
    if (e < E) atomicAdd(&g_deg[ei[e]], 1);
}

__global__ void scan_kernel(int E) {
    const int T = 1024;
    const int CH = (NNODES + T - 1) / T;
    int t = threadIdx.x;
    int beg = t * CH;
    int end = beg + CH; if (end > NNODES) end = NNODES;
    if (beg > NNODES) beg = NNODES;

    int sum = 0;
    for (int i = beg; i < end; i++) sum += g_deg[i];

    __shared__ int sh[1024];
    sh[t] = sum;
    __syncthreads();
    for (int off = 1; off < T; off <<= 1) {
        int v = (t >= off) ? sh[t - off] : 0;
        __syncthreads();
        sh[t] += v;
        __syncthreads();
    }
    int offset = sh[t] - sum;

    int running = offset;
    for (int i = beg; i < end; i++) {
        g_rowptr[i] = running;
        g_fill[i]   = running;
        g_dinv[i]   = rsqrtf((float)(g_deg[i] + 1));   // +1 self-loop
        running += g_deg[i];
    }
    if (t == T - 1) g_rowptr[NNODES] = sh[T - 1];
}

__global__ void scatter_kernel(const int* __restrict__ ei, int E) {
    int e = blockIdx.x * blockDim.x + threadIdx.x;
    if (e >= E) return;
    int r = ei[e];          // destination
    int c = ei[E + e];      // source
    int pos = atomicAdd(&g_fill[r], 1);
    g_colidx[pos] = c;
    g_ew[pos] = g_dinv[r] * g_dinv[c];
}

// ---------------- bf16 split conversion ----------------
__global__ void convert_x_kernel(const float* __restrict__ X) {
    int i = blockIdx.x * blockDim.x + threadIdx.x;     // float4 index
    const int total = NNODES * FIN / 4;
    if (i >= total) return;
    float4 v = ((const float4*)X)[i];
    __nv_bfloat16 h0 = __float2bfloat16(v.x);
    __nv_bfloat16 h1 = __float2bfloat16(v.y);
    __nv_bfloat16 h2 = __float2bfloat16(v.z);
    __nv_bfloat16 h3 = __float2bfloat16(v.w);
    __nv_bfloat16 l0 = __float2bfloat16(v.x - __bfloat162float(h0));
    __nv_bfloat16 l1 = __float2bfloat16(v.y - __bfloat162float(h1));
    __nv_bfloat16 l2 = __float2bfloat16(v.z - __bfloat162float(h2));
    __nv_bfloat16 l3 = __float2bfloat16(v.w - __bfloat162float(h3));
    __nv_bfloat162* ah2 = (__nv_bfloat162*)g_ah;
    __nv_bfloat162* al2 = (__nv_bfloat162*)g_al;
    ah2[2 * i]     = __nv_bfloat162(h0, h1);
    ah2[2 * i + 1] = __nv_bfloat162(h2, h3);
    al2[2 * i]     = __nv_bfloat162(l0, l1);
    al2[2 * i + 1] = __nv_bfloat162(l2, l3);
}

__global__ void convert_w_kernel(const float* __restrict__ W1) {
    int i = blockIdx.x * blockDim.x + threadIdx.x;     // over FIN*HID
    if (i >= FIN * HID) return;
    int k = i / HID, n = i - k * HID;
    float v = W1[i];
    __nv_bfloat16 h = __float2bfloat16(v);
    g_whT[n * FIN + k] = h;
    g_wlT[n * FIN + k] = __float2bfloat16(v - __bfloat162float(h));
}

// ---------------- helpers for mma path ----------------
__device__ __forceinline__ unsigned smem_u32(const void* p) {
    return (unsigned)__cvta_generic_to_shared(p);
}
__device__ __forceinline__ void cpasync16(unsigned saddr, const void* gaddr) {
    asm volatile("cp.async.cg.shared.global [%0], [%1], 16;\n" :: "r"(saddr), "l"(gaddr));
}
__device__ __forceinline__ void ldmatrix_x4(unsigned* r, unsigned addr) {
    asm volatile("ldmatrix.sync.aligned.m8n8.x4.shared.b16 {%0,%1,%2,%3}, [%4];\n"
                 : "=r"(r[0]), "=r"(r[1]), "=r"(r[2]), "=r"(r[3]) : "r"(addr));
}
__device__ __forceinline__ void mma_bf16(float* d, const unsigned* a, const unsigned* b) {
    asm volatile("mma.sync.aligned.m16n8k16.row.col.f32.bf16.bf16.f32 "
                 "{%0,%1,%2,%3}, {%4,%5,%6,%7}, {%8,%9}, {%0,%1,%2,%3};\n"
                 : "+f"(d[0]), "+f"(d[1]), "+f"(d[2]), "+f"(d[3])
                 : "r"(a[0]), "r"(a[1]), "r"(a[2]), "r"(a[3]), "r"(b[0]), "r"(b[1]));
}

// ---------------- GEMM1 via tensor cores, bf16-split (3 segments, K'=1536) ----------
// h1 = relu(x@W1 + b1) ~= relu(ah@wh + al@wh + ah@wl + b1)
// BM=128 BN=128 BK=32, 256 threads (8 warps, 4m x 2n, warp tile 32x64)
#define ASTRIDE 40          // smem row stride in bf16 elements (80B): conflict-free ldmatrix
#define NTILES  48          // 3 segments x (512/32)

__global__ __launch_bounds__(256) void gemm1_mma_kernel(const float* __restrict__ b1) {
    __shared__ __nv_bfloat16 sA[2][128 * ASTRIDE];
    __shared__ __nv_bfloat16 sB[2][128 * ASTRIDE];

    const int tid  = threadIdx.x;
    const int lane = tid & 31;
    const int wid  = tid >> 5;
    const int wm   = wid & 3;     // 4 warps along M
    const int wn   = wid >> 2;    // 2 warps along N
    const int m0 = blockIdx.x * 128;
    const int n0 = blockIdx.y * 128;

    unsigned sAaddr[2] = { smem_u32(sA[0]), smem_u32(sA[1]) };
    unsigned sBaddr[2] = { smem_u32(sB[0]), smem_u32(sB[1]) };

    float acc[2][8][4];
    #pragma unroll
    for (int mf = 0; mf < 2; mf++)
        #pragma unroll
        for (int nf = 0; nf < 8; nf++)
            #pragma unroll
            for (int q = 0; q < 4; q++) acc[mf][nf][q] = 0.0f;

    auto issue_tile = [&](int i, int buf) {
        int seg = i >> 4, kt = i & 15;
        const __nv_bfloat16* Aseg = (seg == 1) ? g_al : g_ah;
        const __nv_bfloat16* Bseg = (seg == 2) ? g_wlT : g_whT;
        int k0 = kt * 32;
        #pragma unroll
        for (int p = 0; p < 2; p++) {
            int r  = (tid >> 2) + p * 64;     // 0..127
            int ch = tid & 3;                 // 16B chunk within 64B row-slice
            int arow = m0 + r; if (arow > NNODES - 1) arow = NNODES - 1;
            cpasync16(sAaddr[buf] + (unsigned)((r * ASTRIDE + ch * 8) * 2),
                      Aseg + (size_t)arow * FIN + k0 + ch * 8);
            cpasync16(sBaddr[buf] + (unsigned)((r * ASTRIDE + ch * 8) * 2),
                      Bseg + (size_t)(n0 + r) * FIN + k0 + ch * 8);
        }
        asm volatile("cp.async.commit_group;\n" ::);
    };

    auto compute_tile = [&](int buf) {
        unsigned abase = sAaddr[buf], bbase = sBaddr[buf];
        #pragma unroll
        for (int ks = 0; ks < 2; ks++) {
            unsigned ar[2][4];
            #pragma unroll
            for (int mf = 0; mf < 2; mf++) {
                int row  = wm * 32 + mf * 16 + (lane & 15);
                int colh = lane >> 4;
                ldmatrix_x4(ar[mf], abase + (unsigned)((row * ASTRIDE + ks * 16 + colh * 8) * 2));
            }
            unsigned br[8][2];
            #pragma unroll
            for (int np = 0; np < 4; np++) {
                int mat = lane >> 3, rr = lane & 7;
                int n  = wn * 64 + np * 16 + (mat >> 1) * 8 + rr;
                int kh = mat & 1;
                unsigned t[4];
                ldmatrix_x4(t, bbase + (unsigned)((n * ASTRIDE + ks * 16 + kh * 8) * 2));
                br[np * 2][0] = t[0];     br[np * 2][1] = t[1];
                br[np * 2 + 1][0] = t[2]; br[np * 2 + 1][1] = t[3];
            }
            #pragma unroll
            for (int mf = 0; mf < 2; mf++)
                #pragma unroll
                for (int nf = 0; nf < 8; nf++)
                    mma_bf16(acc[mf][nf], ar[mf], br[nf]);
        }
    };

    issue_tile(0, 0);
    for (int i = 0; i < NTILES; i++) {
        if (i + 1 < NTILES) issue_tile(i + 1, (i + 1) & 1);
        if (i + 1 < NTILES) asm volatile("cp.async.wait_group 1;\n" ::);
        else                asm volatile("cp.async.wait_group 0;\n" ::);
        __syncthreads();
        compute_tile(i & 1);
        __syncthreads();
    }

    // epilogue: relu(acc + bias) -> g_hid fp32
    const int g  = lane >> 2;          // accum row within 8
    const int c2 = (lane & 3) * 2;     // accum col pair
    #pragma unroll
    for (int mf = 0; mf < 2; mf++) {
        #pragma unroll
        for (int nf = 0; nf < 8; nf++) {
            int n = n0 + wn * 64 + nf * 8 + c2;
            float bn0 = b1[n], bn1 = b1[n + 1];
            int m_lo = m0 + wm * 32 + mf * 16 + g;
            int m_hi = m_lo + 8;
            if (m_lo < NNODES) {
                float2 v = make_float2(fmaxf(acc[mf][nf][0] + bn0, 0.0f),
                                       fmaxf(acc[mf][nf][1] + bn1, 0.0f));
                *(float2*)&g_hid[(size_t)m_lo * HID + n] = v;
            }
            if (m_hi < NNODES) {
                float2 v = make_float2(fmaxf(acc[mf][nf][2] + bn0, 0.0f),
                                       fmaxf(acc[mf][nf][3] + bn1, 0.0f));
                *(float2*)&g_hid[(size_t)m_hi * HID + n] = v;
            }
        }
    }
}

// ---------------- GEMM2: h = hid @ W2 + b2  [100000,256]x[256,40] (round-1 form) ----
__global__ __launch_bounds__(256) void gemm2_kernel(
    const float* __restrict__ W2, const float* __restrict__ b2)
{
    __shared__ float Hs[32][65];
    __shared__ float Ws[32][40];

    int tid = threadIdx.x;
    int m0 = blockIdx.x * 64;
    int tx = tid & 7;        // 8 -> 5 cols each
    int ty = tid >> 3;       // 32 -> 2 rows each

    float acc[2][5];
    #pragma unroll
    for (int r = 0; r < 2; r++)
        #pragma unroll
        for (int j = 0; j < 5; j++) acc[r][j] = 0.0f;

    for (int k0 = 0; k0 < HID; k0 += 32) {
        {
            int kk = tid & 31;
            int mb = tid >> 5;   // 0..7
            #pragma unroll
            for (int mi = 0; mi < 8; mi++) {
                int m = mi * 8 + mb;
                float v = 0.0f;
                if (m0 + m < NNODES)
                    v = g_hid[(size_t)(m0 + m) * HID + k0 + kk];
                Hs[kk][m] = v;
            }
        }
        #pragma unroll
        for (int l = 0; l < 5; l++) {
            int idx = tid + l * 256;
            int kr = idx / 40;
            int n = idx - kr * 40;
            Ws[kr][n] = W2[(size_t)(k0 + kr) * NC + n];
        }
        __syncthreads();

        #pragma unroll
        for (int k = 0; k < 32; k++) {
            float a0 = Hs[k][ty * 2];
            float a1 = Hs[k][ty * 2 + 1];
            #pragma unroll
            for (int j = 0; j < 5; j++) {
                float b = Ws[k][tx * 5 + j];
                acc[0][j] += a0 * b;
                acc[1][j] += a1 * b;
            }
        }
        __syncthreads();
    }

    #pragma unroll
    for (int r = 0; r < 2; r++) {
        int m = m0 + ty * 2 + r;
        if (m < NNODES) {
            #pragma unroll
            for (int j = 0; j < 5; j++) {
                int n = tx * 5 + j;
                g_h[(size_t)m * NC + n] = acc[r][j] + b2[n];
            }
        }
    }
}

// ---------------- APPNP propagation step (round-1 form) ----------------
__global__ __launch_bounds__(256) void spmm_kernel(int srcSel, int dstSel) {
    const float* zin  = (srcSel == 0) ? g_h : (srcSel == 1 ? g_zA : g_zB);
    float*       zout = (dstSel == 1) ? g_zA : g_zB;

    int w = (blockIdx.x * blockDim.x + threadIdx.x) >> 5;
    int lane = threadIdx.x & 31;
    if (w >= NNODES) return;
    int r = w;
    int s = g_rowptr[r];
    int e = g_rowptr[r + 1];

    float acc0 = 0.0f, acc1 = 0.0f;
    for (int j = s; j < e; j++) {
        float wt = g_ew[j];
        int ci = g_colidx[j];
        const float* zb = zin + (size_t)ci * NC;
        acc0 += wt * zb[lane];
        if (lane < 8) acc1 += wt * zb[32 + lane];
    }
    float dv = g_dinv[r];
    float ws = dv * dv;
    const float* zr = zin + (size_t)r * NC;
    acc0 += ws * zr[lane];
    if (lane < 8) acc1 += ws * zr[32 + lane];

    const float* hr = g_h + (size_t)r * NC;
    float* zo = zout + (size_t)r * NC;
    zo[lane] = (1.0f - ALPHA) * acc0 + ALPHA * hr[lane];
    if (lane < 8) zo[32 + lane] = (1.0f - ALPHA) * acc1 + ALPHA * hr[32 + lane];
}

// ---------------- log_softmax over 40 classes, warp per row ----------------
__global__ __launch_bounds__(256) void logsoftmax_kernel(float* __restrict__ out) {
    int w = (blockIdx.x * blockDim.x + threadIdx.x) >> 5;
    int lane = threadIdx.x & 31;
    if (w >= NNODES) return;

    const float* zr = g_zB + (size_t)w * NC;
    float v0 = zr[lane];
    float v1 = (lane < 8) ? zr[32 + lane] : -3.4e38f;

    float m = fmaxf(v0, v1);
    #pragma unroll
    for (int off = 16; off > 0; off >>= 1)
        m = fmaxf(m, __shfl_xor_sync(0xffffffff, m, off));

    float s = __expf(v0 - m) + ((lane < 8) ? __expf(v1 - m) : 0.0f);
    #pragma unroll
    for (int off = 16; off > 0; off >>= 1)
        s += __shfl_xor_sync(0xffffffff, s, off);

    float lse = m + logf(s);
    float* o = out + (size_t)w * NC;
    o[lane] = v0 - lse;
    if (lane < 8) o[32 + lane] = v1 - lse;
}

// ---------------- launch ----------------
extern "C" void kernel_launch(void* const* d_in, const int* in_sizes, int n_in,
                              void* d_out, int out_size) {
    const float* x  = (const float*)d_in[0];
    const float* W1 = (const float*)d_in[1];
    const float* b1 = (const float*)d_in[2];
    const float* W2 = (const float*)d_in[3];
    const float* b2 = (const float*)d_in[4];
    const int*   ei = (const int*)d_in[5];
    float* out = (float*)d_out;
    int E = in_sizes[5] / 2;

    // graph preprocessing -> CSR + normalized weights
    zero_deg_kernel<<<(NNODES + 255) / 256, 256>>>();
    count_deg_kernel<<<(E + 255) / 256, 256>>>(ei, E);
    scan_kernel<<<1, 1024>>>(E);
    scatter_kernel<<<(E + 255) / 256, 256>>>(ei, E);

    // bf16 split conversion for tensor-core gemm1
    convert_x_kernel<<<(NNODES * FIN / 4 + 255) / 256, 256>>>(x);
    convert_w_kernel<<<(FIN * HID + 255) / 256, 256>>>(W1);

    // MLP encoder
    dim3 g1((NNODES + 127) / 128, HID / 128);
    gemm1_mma_kernel<<<g1, 256>>>(b1);
    gemm2_kernel<<<(NNODES + 63) / 64, 256>>>(W2, b2);

    // K=10 APPNP steps; src: 0=h 1=zA 2=zB, dst: 1=zA 2=zB
    int spmmGrid = (NNODES * 32 + 255) / 256;
    for (int i = 1; i <= KSTEPS; i++) {
        int src = (i == 1) ? 0 : ((i & 1) ? 2 : 1);
        int dst = (i & 1) ? 1 : 2;
        spmm_kernel<<<spmmGrid, 256>>>(src, dst);
    }

    // final z is in g_zB (K even)
    logsoftmax_kernel<<<spmmGrid, 256>>>(out);
}

// round 7
// speedup vs baseline: 1.5024x; 1.1412x over previous
#include <cuda_runtime.h>
#include <cuda_bf16.h>
#include <math.h>

#define NNODES 100000
#define FIN    512
#define HID    256
#define NC     40
#define KSTEPS 10
#define EMAX   3200000
#define ALPHA  0.1f

// ---------------- device scratch (no allocations allowed) ----------------
__device__ float g_hid[NNODES * HID];      // ~102 MB
__device__ float g_h  [NNODES * NC];       // 16 MB
__device__ float g_zA [NNODES * NC];
__device__ float g_zB [NNODES * NC];
__device__ float g_dinv[NNODES];
__device__ int   g_deg [NNODES];
__device__ int   g_rowptr[NNODES + 1];
__device__ int   g_fill[NNODES];
__device__ int2  g_edge[EMAX];             // (col, ew bits) packed

// bf16 split operands for tensor-core gemm1
__device__ __nv_bfloat16 g_ah [NNODES * FIN];   // 102 MB
__device__ __nv_bfloat16 g_al [NNODES * FIN];   // 102 MB
__device__ __nv_bfloat16 g_whT[HID * FIN];      // [n][k]
__device__ __nv_bfloat16 g_wlT[HID * FIN];

// ---------------- graph preprocessing ----------------
__global__ void zero_deg_kernel() {
    int i = blockIdx.x * blockDim.x + threadIdx.x;
    if (i < NNODES) g_deg[i] = 0;
}

__global__ void count_deg_kernel(const int* __restrict__ ei, int E) {
    int e = blockIdx.x * blockDim.x + threadIdx.x;
    if (e < E) atomicAdd(&g_deg[ei[e]], 1);
}

__global__ void scan_kernel(int E) {
    const int T = 1024;
    const int CH = (NNODES + T - 1) / T;
    int t = threadIdx.x;
    int beg = t * CH;
    int end = beg + CH; if (end > NNODES) end = NNODES;
    if (beg > NNODES) beg = NNODES;

    int sum = 0;
    for (int i = beg; i < end; i++) sum += g_deg[i];

    __shared__ int sh[1024];
    sh[t] = sum;
    __syncthreads();
    for (int off = 1; off < T; off <<= 1) {
        int v = (t >= off) ? sh[t - off] : 0;
        __syncthreads();
        sh[t] += v;
        __syncthreads();
    }
    int offset = sh[t] - sum;

    int running = offset;
    for (int i = beg; i < end; i++) {
        g_rowptr[i] = running;
        g_fill[i]   = running;
        g_dinv[i]   = rsqrtf((float)(g_deg[i] + 1));   // +1 self-loop
        running += g_deg[i];
    }
    if (t == T - 1) g_rowptr[NNODES] = sh[T - 1];
}

__global__ void scatter_kernel(const int* __restrict__ ei, int E) {
    int e = blockIdx.x * blockDim.x + threadIdx.x;
    if (e >= E) return;
    int r = ei[e];          // destination
    int c = ei[E + e];      // source
    int pos = atomicAdd(&g_fill[r], 1);
    g_edge[pos] = make_int2(c, __float_as_int(g_dinv[r] * g_dinv[c]));
}

// ---------------- bf16 split conversion ----------------
__global__ void convert_x_kernel(const float* __restrict__ X) {
    int i = blockIdx.x * blockDim.x + threadIdx.x;     // float4 index
    const int total = NNODES * FIN / 4;
    if (i >= total) return;
    float4 v = ((const float4*)X)[i];
    __nv_bfloat16 h0 = __float2bfloat16(v.x);
    __nv_bfloat16 h1 = __float2bfloat16(v.y);
    __nv_bfloat16 h2 = __float2bfloat16(v.z);
    __nv_bfloat16 h3 = __float2bfloat16(v.w);
    __nv_bfloat16 l0 = __float2bfloat16(v.x - __bfloat162float(h0));
    __nv_bfloat16 l1 = __float2bfloat16(v.y - __bfloat162float(h1));
    __nv_bfloat16 l2 = __float2bfloat16(v.z - __bfloat162float(h2));
    __nv_bfloat16 l3 = __float2bfloat16(v.w - __bfloat162float(h3));
    __nv_bfloat162* ah2 = (__nv_bfloat162*)g_ah;
    __nv_bfloat162* al2 = (__nv_bfloat162*)g_al;
    ah2[2 * i]     = __nv_bfloat162(h0, h1);
    ah2[2 * i + 1] = __nv_bfloat162(h2, h3);
    al2[2 * i]     = __nv_bfloat162(l0, l1);
    al2[2 * i + 1] = __nv_bfloat162(l2, l3);
}

__global__ void convert_w_kernel(const float* __restrict__ W1) {
    int i = blockIdx.x * blockDim.x + threadIdx.x;     // over FIN*HID
    if (i >= FIN * HID) return;
    int k = i / HID, n = i - k * HID;
    float v = W1[i];
    __nv_bfloat16 h = __float2bfloat16(v);
    g_whT[n * FIN + k] = h;
    g_wlT[n * FIN + k] = __float2bfloat16(v - __bfloat162float(h));
}

// ---------------- helpers for mma path ----------------
__device__ __forceinline__ unsigned smem_u32(const void* p) {
    return (unsigned)__cvta_generic_to_shared(p);
}
__device__ __forceinline__ void cpasync16(unsigned saddr, const void* gaddr) {
    asm volatile("cp.async.cg.shared.global [%0], [%1], 16;\n" :: "r"(saddr), "l"(gaddr));
}
__device__ __forceinline__ void ldmatrix_x4(unsigned* r, unsigned addr) {
    asm volatile("ldmatrix.sync.aligned.m8n8.x4.shared.b16 {%0,%1,%2,%3}, [%4];\n"
                 : "=r"(r[0]), "=r"(r[1]), "=r"(r[2]), "=r"(r[3]) : "r"(addr));
}
__device__ __forceinline__ void mma_bf16(float* d, const unsigned* a, const unsigned* b) {
    asm volatile("mma.sync.aligned.m16n8k16.row.col.f32.bf16.bf16.f32 "
                 "{%0,%1,%2,%3}, {%4,%5,%6,%7}, {%8,%9}, {%0,%1,%2,%3};\n"
                 : "+f"(d[0]), "+f"(d[1]), "+f"(d[2]), "+f"(d[3])
                 : "r"(a[0]), "r"(a[1]), "r"(a[2]), "r"(a[3]), "r"(b[0]), "r"(b[1]));
}

// ---------------- GEMM1 via tensor cores, bf16-split (3 segments, K'=1536) ----------
// h1 = relu(x@W1 + b1) ~= relu(ah@wh + al@wh + ah@wl + b1)
// BM=128 BN=128 BK=32, 256 threads (8 warps, 4m x 2n, warp tile 32x64)
#define ASTRIDE 40          // smem row stride in bf16 elements (80B): conflict-free ldmatrix
#define NTILES  48          // 3 segments x (512/32)

__global__ __launch_bounds__(256) void gemm1_mma_kernel(const float* __restrict__ b1) {
    __shared__ __nv_bfloat16 sA[2][128 * ASTRIDE];
    __shared__ __nv_bfloat16 sB[2][128 * ASTRIDE];

    const int tid  = threadIdx.x;
    const int lane = tid & 31;
    const int wid  = tid >> 5;
    const int wm   = wid & 3;     // 4 warps along M
    const int wn   = wid >> 2;    // 2 warps along N
    const int m0 = blockIdx.x * 128;
    const int n0 = blockIdx.y * 128;

    unsigned sAaddr[2] = { smem_u32(sA[0]), smem_u32(sA[1]) };
    unsigned sBaddr[2] = { smem_u32(sB[0]), smem_u32(sB[1]) };

    float acc[2][8][4];
    #pragma unroll
    for (int mf = 0; mf < 2; mf++)
        #pragma unroll
        for (int nf = 0; nf < 8; nf++)
            #pragma unroll
            for (int q = 0; q < 4; q++) acc[mf][nf][q] = 0.0f;

    auto issue_tile = [&](int i, int buf) {
        int seg = i >> 4, kt = i & 15;
        const __nv_bfloat16* Aseg = (seg == 1) ? g_al : g_ah;
        const __nv_bfloat16* Bseg = (seg == 2) ? g_wlT : g_whT;
        int k0 = kt * 32;
        #pragma unroll
        for (int p = 0; p < 2; p++) {
            int r  = (tid >> 2) + p * 64;     // 0..127
            int ch = tid & 3;                 // 16B chunk within 64B row-slice
            int arow = m0 + r; if (arow > NNODES - 1) arow = NNODES - 1;
            cpasync16(sAaddr[buf] + (unsigned)((r * ASTRIDE + ch * 8) * 2),
                      Aseg + (size_t)arow * FIN + k0 + ch * 8);
            cpasync16(sBaddr[buf] + (unsigned)((r * ASTRIDE + ch * 8) * 2),
                      Bseg + (size_t)(n0 + r) * FIN + k0 + ch * 8);
        }
        asm volatile("cp.async.commit_group;\n" ::);
    };

    auto compute_tile = [&](int buf) {
        unsigned abase = sAaddr[buf], bbase = sBaddr[buf];
        #pragma unroll
        for (int ks = 0; ks < 2; ks++) {
            unsigned ar[2][4];
            #pragma unroll
            for (int mf = 0; mf < 2; mf++) {
                int row  = wm * 32 + mf * 16 + (lane & 15);
                int colh = lane >> 4;
                ldmatrix_x4(ar[mf], abase + (unsigned)((row * ASTRIDE + ks * 16 + colh * 8) * 2));
            }
            unsigned br[8][2];
            #pragma unroll
            for (int np = 0; np < 4; np++) {
                int mat = lane >> 3, rr = lane & 7;
                int n  = wn * 64 + np * 16 + (mat >> 1) * 8 + rr;
                int kh = mat & 1;
                unsigned t[4];
                ldmatrix_x4(t, bbase + (unsigned)((n * ASTRIDE + ks * 16 + kh * 8) * 2));
                br[np * 2][0] = t[0];     br[np * 2][1] = t[1];
                br[np * 2 + 1][0] = t[2]; br[np * 2 + 1][1] = t[3];
            }
            #pragma unroll
            for (int mf = 0; mf < 2; mf++)
                #pragma unroll
                for (int nf = 0; nf < 8; nf++)
                    mma_bf16(acc[mf][nf], ar[mf], br[nf]);
        }
    };

    issue_tile(0, 0);
    for (int i = 0; i < NTILES; i++) {
        if (i + 1 < NTILES) issue_tile(i + 1, (i + 1) & 1);
        if (i + 1 < NTILES) asm volatile("cp.async.wait_group 1;\n" ::);
        else                asm volatile("cp.async.wait_group 0;\n" ::);
        __syncthreads();
        compute_tile(i & 1);
        __syncthreads();
    }

    // epilogue: relu(acc + bias) -> g_hid fp32
    const int g  = lane >> 2;          // accum row within 8
    const int c2 = (lane & 3) * 2;     // accum col pair
    #pragma unroll
    for (int mf = 0; mf < 2; mf++) {
        #pragma unroll
        for (int nf = 0; nf < 8; nf++) {
            int n = n0 + wn * 64 + nf * 8 + c2;
            float bn0 = b1[n], bn1 = b1[n + 1];
            int m_lo = m0 + wm * 32 + mf * 16 + g;
            int m_hi = m_lo + 8;
            if (m_lo < NNODES) {
                float2 v = make_float2(fmaxf(acc[mf][nf][0] + bn0, 0.0f),
                                       fmaxf(acc[mf][nf][1] + bn1, 0.0f));
                *(float2*)&g_hid[(size_t)m_lo * HID + n] = v;
            }
            if (m_hi < NNODES) {
                float2 v = make_float2(fmaxf(acc[mf][nf][2] + bn0, 0.0f),
                                       fmaxf(acc[mf][nf][3] + bn1, 0.0f));
                *(float2*)&g_hid[(size_t)m_hi * HID + n] = v;
            }
        }
    }
}

// ---------------- GEMM2: h = hid @ W2 + b2  [100000,256]x[256,40] ----------------
__global__ __launch_bounds__(256) void gemm2_kernel(
    const float* __restrict__ W2, const float* __restrict__ b2)
{
    __shared__ float Hs[32][65];
    __shared__ float Ws[32][40];

    int tid = threadIdx.x;
    int m0 = blockIdx.x * 64;
    int tx = tid & 7;        // 8 -> 5 cols each
    int ty = tid >> 3;       // 32 -> 2 rows each

    float acc[2][5];
    #pragma unroll
    for (int r = 0; r < 2; r++)
        #pragma unroll
        for (int j = 0; j < 5; j++) acc[r][j] = 0.0f;

    for (int k0 = 0; k0 < HID; k0 += 32) {
        {
            int kk = tid & 31;
            int mb = tid >> 5;   // 0..7
            #pragma unroll
            for (int mi = 0; mi < 8; mi++) {
                int m = mi * 8 + mb;
                float v = 0.0f;
                if (m0 + m < NNODES)
                    v = g_hid[(size_t)(m0 + m) * HID + k0 + kk];
                Hs[kk][m] = v;
            }
        }
        #pragma unroll
        for (int l = 0; l < 5; l++) {
            int idx = tid + l * 256;
            int kr = idx / 40;
            int n = idx - kr * 40;
            Ws[kr][n] = W2[(size_t)(k0 + kr) * NC + n];
        }
        __syncthreads();

        #pragma unroll
        for (int k = 0; k < 32; k++) {
            float a0 = Hs[k][ty * 2];
            float a1 = Hs[k][ty * 2 + 1];
            #pragma unroll
            for (int j = 0; j < 5; j++) {
                float b = Ws[k][tx * 5 + j];
                acc[0][j] += a0 * b;
                acc[1][j] += a1 * b;
            }
        }
        __syncthreads();
    }

    #pragma unroll
    for (int r = 0; r < 2; r++) {
        int m = m0 + ty * 2 + r;
        if (m < NNODES) {
            #pragma unroll
            for (int j = 0; j < 5; j++) {
                int n = tx * 5 + j;
                g_h[(size_t)m * NC + n] = acc[r][j] + b2[n];
            }
        }
    }
}

// ---------------- APPNP propagation step: zout = 0.9*A_norm*zin + 0.1*h ----------------
// warp per row; 3 edge sub-groups of 10 lanes, each lane owns one float4 (4 channels)
__global__ __launch_bounds__(256) void spmm_kernel(int srcSel, int dstSel) {
    const float* zin  = (srcSel == 0) ? g_h : (srcSel == 1 ? g_zA : g_zB);
    float*       zout = (dstSel == 1) ? g_zA : g_zB;

    int w = (blockIdx.x * blockDim.x + threadIdx.x) >> 5;
    int lane = threadIdx.x & 31;
    if (w >= NNODES) return;
    int s = g_rowptr[w];
    int e = g_rowptr[w + 1];

    int sub = lane / 10;          // 0..2 active, 3 for lanes 30,31 (idle)
    int cg  = lane - sub * 10;    // channel group 0..9 -> channels cg*4..cg*4+3

    float4 acc = make_float4(0.f, 0.f, 0.f, 0.f);
    if (sub < 3) {
        for (int j = s + sub; j < e; j += 3) {
            int2 ed = __ldg(&g_edge[j]);
            float wt = __int_as_float(ed.y);
            float4 zv = *(const float4*)(zin + (size_t)ed.x * NC + cg * 4);
            acc.x += wt * zv.x;
            acc.y += wt * zv.y;
            acc.z += wt * zv.z;
            acc.w += wt * zv.w;
        }
    }

    // reduce the 3 sub-group partials: lane l (<10) needs l, l+10, l+20.
    // shuffle from ORIGINAL values only (no chained adds -> no OOR aliasing).
    float tx1 = __shfl_down_sync(0xffffffff, acc.x, 10);
    float ty1 = __shfl_down_sync(0xffffffff, acc.y, 10);
    float tz1 = __shfl_down_sync(0xffffffff, acc.z, 10);
    float tw1 = __shfl_down_sync(0xffffffff, acc.w, 10);
    float tx2 = __shfl_down_sync(0xffffffff, acc.x, 20);
    float ty2 = __shfl_down_sync(0xffffffff, acc.y, 20);
    float tz2 = __shfl_down_sync(0xffffffff, acc.z, 20);
    float tw2 = __shfl_down_sync(0xffffffff, acc.w, 20);

    if (lane < 10) {
        acc.x += tx1 + tx2;
        acc.y += ty1 + ty2;
        acc.z += tz1 + tz2;
        acc.w += tw1 + tw2;

        // self loop
        float dv = g_dinv[w];
        float ws = dv * dv;
        float4 zr = *(const float4*)(zin + (size_t)w * NC + cg * 4);
        acc.x += ws * zr.x;
        acc.y += ws * zr.y;
        acc.z += ws * zr.z;
        acc.w += ws * zr.w;

        float4 hr = *(const float4*)(g_h + (size_t)w * NC + cg * 4);
        float4 o;
        o.x = (1.0f - ALPHA) * acc.x + ALPHA * hr.x;
        o.y = (1.0f - ALPHA) * acc.y + ALPHA * hr.y;
        o.z = (1.0f - ALPHA) * acc.z + ALPHA * hr.z;
        o.w = (1.0f - ALPHA) * acc.w + ALPHA * hr.w;
        *(float4*)(zout + (size_t)w * NC + cg * 4) = o;
    }
}

// ---------------- log_softmax over 40 classes, warp per row ----------------
__global__ __launch_bounds__(256) void logsoftmax_kernel(float* __restrict__ out) {
    int w = (blockIdx.x * blockDim.x + threadIdx.x) >> 5;
    int lane = threadIdx.x & 31;
    if (w >= NNODES) return;

    const float* zr = g_zB + (size_t)w * NC;
    float v0 = zr[lane];
    float v1 = (lane < 8) ? zr[32 + lane] : -3.4e38f;

    float m = fmaxf(v0, v1);
    #pragma unroll
    for (int off = 16; off > 0; off >>= 1)
        m = fmaxf(m, __shfl_xor_sync(0xffffffff, m, off));

    float s = __expf(v0 - m) + ((lane < 8) ? __expf(v1 - m) : 0.0f);
    #pragma unroll
    for (int off = 16; off > 0; off >>= 1)
        s += __shfl_xor_sync(0xffffffff, s, off);

    float lse = m + logf(s);
    float* o = out + (size_t)w * NC;
    o[lane] = v0 - lse;
    if (lane < 8) o[32 + lane] = v1 - lse;
}

// ---------------- launch ----------------
extern "C" void kernel_launch(void* const* d_in, const int* in_sizes, int n_in,
                              void* d_out, int out_size) {
    const float* x  = (const float*)d_in[0];
    const float* W1 = (const float*)d_in[1];
    const float* b1 = (const float*)d_in[2];
    const float* W2 = (const float*)d_in[3];
    const float* b2 = (const float*)d_in[4];
    const int*   ei = (const int*)d_in[5];
    float* out = (float*)d_out;
    int E = in_sizes[5] / 2;

    // graph preprocessing -> CSR + normalized weights
    zero_deg_kernel<<<(NNODES + 255) / 256, 256>>>();
    count_deg_kernel<<<(E + 255) / 256, 256>>>(ei, E);
    scan_kernel<<<1, 1024>>>(E);
    scatter_kernel<<<(E + 255) / 256, 256>>>(ei, E);

    // bf16 split conversion for tensor-core gemm1
    convert_x_kernel<<<(NNODES * FIN / 4 + 255) / 256, 256>>>(x);
    convert_w_kernel<<<(FIN * HID + 255) / 256, 256>>>(W1);

    // MLP encoder
    dim3 g1((NNODES + 127) / 128, HID / 128);
    gemm1_mma_kernel<<<g1, 256>>>(b1);
    gemm2_kernel<<<(NNODES + 63) / 64, 256>>>(W2, b2);

    // K=10 APPNP steps; src: 0=h 1=zA 2=zB, dst: 1=zA 2=zB
    int spmmGrid = (NNODES * 32 + 255) / 256;
    for (int i = 1; i <= KSTEPS; i++) {
        int src = (i == 1) ? 0 : ((i & 1) ? 2 : 1);
        int dst = (i & 1) ? 1 : 2;
        spmm_kernel<<<spmmGrid, 256>>>(src, dst);
    }

    // final z is in g_zB (K even)
    logsoftmax_kernel<<<spmmGrid, 256>>>(out);
}

// round 8
// speedup vs baseline: 1.5272x; 1.0165x over previous
#include <cuda_runtime.h>
#include <cuda_bf16.h>
#include <math.h>

#define NNODES 100000
#define FIN    512
#define HID    256
#define NC     40
#define KSTEPS 10
#define EMAX   3200000
#define ALPHA  0.1f

// ---------------- device scratch (no allocations allowed) ----------------
__device__ float g_hid[NNODES * HID];      // ~102 MB
__device__ float g_h  [NNODES * NC];       // 16 MB
__device__ float g_zA [NNODES * NC];
__device__ float g_zB [NNODES * NC];
__device__ float g_dinv[NNODES];
__device__ int   g_deg [NNODES];
__device__ int   g_rowptr[NNODES + 1];
__device__ int   g_fill[NNODES];
__device__ int2  g_edge[EMAX];             // (col, ew bits) packed

// bf16 split operands for tensor-core gemm1
__device__ __nv_bfloat16 g_ah [NNODES * FIN];   // 102 MB
__device__ __nv_bfloat16 g_al [NNODES * FIN];   // 102 MB
__device__ __nv_bfloat16 g_whT[HID * FIN];      // [n][k]
__device__ __nv_bfloat16 g_wlT[HID * FIN];

// ---------------- graph preprocessing ----------------
__global__ void zero_deg_kernel() {
    int i = blockIdx.x * blockDim.x + threadIdx.x;
    if (i < NNODES) g_deg[i] = 0;
}

__global__ void count_deg_kernel(const int* __restrict__ ei, int E) {
    int e = blockIdx.x * blockDim.x + threadIdx.x;
    if (e < E) atomicAdd(&g_deg[ei[e]], 1);
}

__global__ void scan_kernel(int E) {
    const int T = 1024;
    const int CH = (NNODES + T - 1) / T;
    int t = threadIdx.x;
    int beg = t * CH;
    int end = beg + CH; if (end > NNODES) end = NNODES;
    if (beg > NNODES) beg = NNODES;

    int sum = 0;
    for (int i = beg; i < end; i++) sum += g_deg[i];

    __shared__ int sh[1024];
    sh[t] = sum;
    __syncthreads();
    for (int off = 1; off < T; off <<= 1) {
        int v = (t >= off) ? sh[t - off] : 0;
        __syncthreads();
        sh[t] += v;
        __syncthreads();
    }
    int offset = sh[t] - sum;

    int running = offset;
    for (int i = beg; i < end; i++) {
        g_rowptr[i] = running;
        g_fill[i]   = running;
        g_dinv[i]   = rsqrtf((float)(g_deg[i] + 1));   // +1 self-loop
        running += g_deg[i];
    }
    if (t == T - 1) g_rowptr[NNODES] = sh[T - 1];
}

__global__ void scatter_kernel(const int* __restrict__ ei, int E) {
    int e = blockIdx.x * blockDim.x + threadIdx.x;
    if (e >= E) return;
    int r = ei[e];          // destination
    int c = ei[E + e];      // source
    int pos = atomicAdd(&g_fill[r], 1);
    g_edge[pos] = make_int2(c, __float_as_int(g_dinv[r] * g_dinv[c]));
}

// ---------------- bf16 split conversion ----------------
__global__ void convert_x_kernel(const float* __restrict__ X) {
    int i = blockIdx.x * blockDim.x + threadIdx.x;     // float4 index
    const int total = NNODES * FIN / 4;
    if (i >= total) return;
    float4 v = ((const float4*)X)[i];
    __nv_bfloat16 h0 = __float2bfloat16(v.x);
    __nv_bfloat16 h1 = __float2bfloat16(v.y);
    __nv_bfloat16 h2 = __float2bfloat16(v.z);
    __nv_bfloat16 h3 = __float2bfloat16(v.w);
    __nv_bfloat16 l0 = __float2bfloat16(v.x - __bfloat162float(h0));
    __nv_bfloat16 l1 = __float2bfloat16(v.y - __bfloat162float(h1));
    __nv_bfloat16 l2 = __float2bfloat16(v.z - __bfloat162float(h2));
    __nv_bfloat16 l3 = __float2bfloat16(v.w - __bfloat162float(h3));
    __nv_bfloat162* ah2 = (__nv_bfloat162*)g_ah;
    __nv_bfloat162* al2 = (__nv_bfloat162*)g_al;
    ah2[2 * i]     = __nv_bfloat162(h0, h1);
    ah2[2 * i + 1] = __nv_bfloat162(h2, h3);
    al2[2 * i]     = __nv_bfloat162(l0, l1);
    al2[2 * i + 1] = __nv_bfloat162(l2, l3);
}

__global__ void convert_w_kernel(const float* __restrict__ W1) {
    int i = blockIdx.x * blockDim.x + threadIdx.x;     // over FIN*HID
    if (i >= FIN * HID) return;
    int k = i / HID, n = i - k * HID;
    float v = W1[i];
    __nv_bfloat16 h = __float2bfloat16(v);
    g_whT[n * FIN + k] = h;
    g_wlT[n * FIN + k] = __float2bfloat16(v - __bfloat162float(h));
}

// ---------------- helpers for mma path ----------------
__device__ __forceinline__ unsigned smem_u32(const void* p) {
    return (unsigned)__cvta_generic_to_shared(p);
}
__device__ __forceinline__ void cpasync16(unsigned saddr, const void* gaddr) {
    asm volatile("cp.async.cg.shared.global [%0], [%1], 16;\n" :: "r"(saddr), "l"(gaddr));
}
__device__ __forceinline__ void ldmatrix_x4(unsigned* r, unsigned addr) {
    asm volatile("ldmatrix.sync.aligned.m8n8.x4.shared.b16 {%0,%1,%2,%3}, [%4];\n"
                 : "=r"(r[0]), "=r"(r[1]), "=r"(r[2]), "=r"(r[3]) : "r"(addr));
}
__device__ __forceinline__ void mma_bf16(float* d, const unsigned* a, const unsigned* b) {
    asm volatile("mma.sync.aligned.m16n8k16.row.col.f32.bf16.bf16.f32 "
                 "{%0,%1,%2,%3}, {%4,%5,%6,%7}, {%8,%9}, {%0,%1,%2,%3};\n"
                 : "+f"(d[0]), "+f"(d[1]), "+f"(d[2]), "+f"(d[3])
                 : "r"(a[0]), "r"(a[1]), "r"(a[2]), "r"(a[3]), "r"(b[0]), "r"(b[1]));
}

// swizzled offset within a [rows x 32] bf16 tile (64B rows, 4 x 16B chunks).
// chunk ^= (r>>1)&3  -> conflict-free for all ldmatrix 8-row phases.
__device__ __forceinline__ unsigned swz(int r, int ch) {
    return (unsigned)(r * 64 + ((ch ^ ((r >> 1) & 3)) << 4));
}

// ---------------- GEMM1 via tensor cores, bf16-split (3 segments, K'=1536) ----------
// h1 = relu(x@W1 + b1) ~= relu(ah@wh + al@wh + ah@wl + b1)
// BM=128 BN=256(full HID) BK=32, 512 threads (16 warps, 4m x 4n, warp tile 32x64)
#define NTILES 48           // 3 segments x (512/32)

__global__ __launch_bounds__(512) void gemm1_mma_kernel(const float* __restrict__ b1) {
    __shared__ __nv_bfloat16 sA[2][128 * 32];   // 8KB each, swizzled 64B rows
    __shared__ __nv_bfloat16 sB[2][256 * 32];   // 16KB each

    const int tid  = threadIdx.x;
    const int lane = tid & 31;
    const int wid  = tid >> 5;
    const int wm   = wid & 3;     // 4 warps along M (32 rows each)
    const int wn   = wid >> 2;    // 4 warps along N (64 cols each)
    const int m0 = blockIdx.x * 128;

    unsigned sAaddr[2] = { smem_u32(sA[0]), smem_u32(sA[1]) };
    unsigned sBaddr[2] = { smem_u32(sB[0]), smem_u32(sB[1]) };

    float acc[2][8][4];
    #pragma unroll
    for (int mf = 0; mf < 2; mf++)
        #pragma unroll
        for (int nf = 0; nf < 8; nf++)
            #pragma unroll
            for (int q = 0; q < 4; q++) acc[mf][nf][q] = 0.0f;

    auto issue_tile = [&](int i, int buf) {
        int seg = i >> 4, kt = i & 15;
        const __nv_bfloat16* Aseg = (seg == 1) ? g_al : g_ah;
        const __nv_bfloat16* Bseg = (seg == 2) ? g_wlT : g_whT;
        int k0 = kt * 32;
        // A: 128 rows x 32k = 8KB, one 16B chunk per thread
        {
            int r  = tid >> 2;            // 0..127
            int ch = tid & 3;             // 0..3
            int arow = m0 + r; if (arow > NNODES - 1) arow = NNODES - 1;
            cpasync16(sAaddr[buf] + swz(r, ch),
                      Aseg + (size_t)arow * FIN + k0 + ch * 8);
        }
        // B: 256 rows x 32k = 16KB, two chunks per thread
        #pragma unroll
        for (int p = 0; p < 2; p++) {
            int q = tid + p * 512;
            int r  = q >> 2;              // 0..255
            int ch = q & 3;
            cpasync16(sBaddr[buf] + swz(r, ch),
                      Bseg + (size_t)r * FIN + k0 + ch * 8);
        }
        asm volatile("cp.async.commit_group;\n" ::);
    };

    auto compute_tile = [&](int buf) {
        unsigned abase = sAaddr[buf], bbase = sBaddr[buf];
        #pragma unroll
        for (int ks = 0; ks < 2; ks++) {
            unsigned ar[2][4];
            #pragma unroll
            for (int mf = 0; mf < 2; mf++) {
                int row = wm * 32 + mf * 16 + (lane & 15);
                int ch  = ks * 2 + (lane >> 4);
                ldmatrix_x4(ar[mf], abase + swz(row, ch));
            }
            unsigned br[8][2];
            #pragma unroll
            for (int np = 0; np < 4; np++) {
                int mat = lane >> 3, rr = lane & 7;
                int n  = wn * 64 + np * 16 + (mat >> 1) * 8 + rr;
                int ch = ks * 2 + (mat & 1);
                unsigned t[4];
                ldmatrix_x4(t, bbase + swz(n, ch));
                br[np * 2][0] = t[0];     br[np * 2][1] = t[1];
                br[np * 2 + 1][0] = t[2]; br[np * 2 + 1][1] = t[3];
            }
            #pragma unroll
            for (int mf = 0; mf < 2; mf++)
                #pragma unroll
                for (int nf = 0; nf < 8; nf++)
                    mma_bf16(acc[mf][nf], ar[mf], br[nf]);
        }
    };

    issue_tile(0, 0);
    for (int i = 0; i < NTILES; i++) {
        if (i + 1 < NTILES) issue_tile(i + 1, (i + 1) & 1);
        if (i + 1 < NTILES) asm volatile("cp.async.wait_group 1;\n" ::);
        else                asm volatile("cp.async.wait_group 0;\n" ::);
        __syncthreads();
        compute_tile(i & 1);
        __syncthreads();
    }

    // epilogue: relu(acc + bias) -> g_hid fp32
    const int g  = lane >> 2;          // accum row within 8
    const int c2 = (lane & 3) * 2;     // accum col pair
    #pragma unroll
    for (int mf = 0; mf < 2; mf++) {
        #pragma unroll
        for (int nf = 0; nf < 8; nf++) {
            int n = wn * 64 + nf * 8 + c2;
            float bn0 = b1[n], bn1 = b1[n + 1];
            int m_lo = m0 + wm * 32 + mf * 16 + g;
            int m_hi = m_lo + 8;
            if (m_lo < NNODES) {
                float2 v = make_float2(fmaxf(acc[mf][nf][0] + bn0, 0.0f),
                                       fmaxf(acc[mf][nf][1] + bn1, 0.0f));
                *(float2*)&g_hid[(size_t)m_lo * HID + n] = v;
            }
            if (m_hi < NNODES) {
                float2 v = make_float2(fmaxf(acc[mf][nf][2] + bn0, 0.0f),
                                       fmaxf(acc[mf][nf][3] + bn1, 0.0f));
                *(float2*)&g_hid[(size_t)m_hi * HID + n] = v;
            }
        }
    }
}

// ---------------- GEMM2: h = hid @ W2 + b2  [100000,256]x[256,40] ----------------
__global__ __launch_bounds__(256) void gemm2_kernel(
    const float* __restrict__ W2, const float* __restrict__ b2)
{
    __shared__ float Hs[32][65];
    __shared__ float Ws[32][40];

    int tid = threadIdx.x;
    int m0 = blockIdx.x * 64;
    int tx = tid & 7;        // 8 -> 5 cols each
    int ty = tid >> 3;       // 32 -> 2 rows each

    float acc[2][5];
    #pragma unroll
    for (int r = 0; r < 2; r++)
        #pragma unroll
        for (int j = 0; j < 5; j++) acc[r][j] = 0.0f;

    for (int k0 = 0; k0 < HID; k0 += 32) {
        {
            int kk = tid & 31;
            int mb = tid >> 5;   // 0..7
            #pragma unroll
            for (int mi = 0; mi < 8; mi++) {
                int m = mi * 8 + mb;
                float v = 0.0f;
                if (m0 + m < NNODES)
                    v = g_hid[(size_t)(m0 + m) * HID + k0 + kk];
                Hs[kk][m] = v;
            }
        }
        #pragma unroll
        for (int l = 0; l < 5; l++) {
            int idx = tid + l * 256;
            int kr = idx / 40;
            int n = idx - kr * 40;
            Ws[kr][n] = W2[(size_t)(k0 + kr) * NC + n];
        }
        __syncthreads();

        #pragma unroll
        for (int k = 0; k < 32; k++) {
            float a0 = Hs[k][ty * 2];
            float a1 = Hs[k][ty * 2 + 1];
            #pragma unroll
            for (int j = 0; j < 5; j++) {
                float b = Ws[k][tx * 5 + j];
                acc[0][j] += a0 * b;
                acc[1][j] += a1 * b;
            }
        }
        __syncthreads();
    }

    #pragma unroll
    for (int r = 0; r < 2; r++) {
        int m = m0 + ty * 2 + r;
        if (m < NNODES) {
            #pragma unroll
            for (int j = 0; j < 5; j++) {
                int n = tx * 5 + j;
                g_h[(size_t)m * NC + n] = acc[r][j] + b2[n];
            }
        }
    }
}

// ---------------- APPNP propagation step: zout = 0.9*A_norm*zin + 0.1*h ----------------
// warp per row; 3 edge sub-groups of 10 lanes, each lane owns one float4 (4 channels)
__global__ __launch_bounds__(256) void spmm_kernel(int srcSel, int dstSel) {
    const float* zin  = (srcSel == 0) ? g_h : (srcSel == 1 ? g_zA : g_zB);
    float*       zout = (dstSel == 1) ? g_zA : g_zB;

    int w = (blockIdx.x * blockDim.x + threadIdx.x) >> 5;
    int lane = threadIdx.x & 31;
    if (w >= NNODES) return;
    int s = g_rowptr[w];
    int e = g_rowptr[w + 1];

    int sub = lane / 10;          // 0..2 active, 3 for lanes 30,31 (idle)
    int cg  = lane - sub * 10;    // channel group 0..9 -> channels cg*4..cg*4+3

    float4 acc = make_float4(0.f, 0.f, 0.f, 0.f);
    if (sub < 3) {
        for (int j = s + sub; j < e; j += 3) {
            int2 ed = __ldg(&g_edge[j]);
            float wt = __int_as_float(ed.y);
            float4 zv = *(const float4*)(zin + (size_t)ed.x * NC + cg * 4);
            acc.x += wt * zv.x;
            acc.y += wt * zv.y;
            acc.z += wt * zv.z;
            acc.w += wt * zv.w;
        }
    }

    // reduce the 3 sub-group partials: lane l (<10) needs l, l+10, l+20.
    float tx1 = __shfl_down_sync(0xffffffff, acc.x, 10);
    float ty1 = __shfl_down_sync(0xffffffff, acc.y, 10);
    float tz1 = __shfl_down_sync(0xffffffff, acc.z, 10);
    float tw1 = __shfl_down_sync(0xffffffff, acc.w, 10);
    float tx2 = __shfl_down_sync(0xffffffff, acc.x, 20);
    float ty2 = __shfl_down_sync(0xffffffff, acc.y, 20);
    float tz2 = __shfl_down_sync(0xffffffff, acc.z, 20);
    float tw2 = __shfl_down_sync(0xffffffff, acc.w, 20);

    if (lane < 10) {
        acc.x += tx1 + tx2;
        acc.y += ty1 + ty2;
        acc.z += tz1 + tz2;
        acc.w += tw1 + tw2;

        // self loop
        float dv = g_dinv[w];
        float ws = dv * dv;
        float4 zr = *(const float4*)(zin + (size_t)w * NC + cg * 4);
        acc.x += ws * zr.x;
        acc.y += ws * zr.y;
        acc.z += ws * zr.z;
        acc.w += ws * zr.w;

        float4 hr = *(const float4*)(g_h + (size_t)w * NC + cg * 4);
        float4 o;
        o.x = (1.0f - ALPHA) * acc.x + ALPHA * hr.x;
        o.y = (1.0f - ALPHA) * acc.y + ALPHA * hr.y;
        o.z = (1.0f - ALPHA) * acc.z + ALPHA * hr.z;
        o.w = (1.0f - ALPHA) * acc.w + ALPHA * hr.w;
        *(float4*)(zout + (size_t)w * NC + cg * 4) = o;
    }
}

// ---------------- log_softmax over 40 classes, warp per row ----------------
__global__ __launch_bounds__(256) void logsoftmax_kernel(float* __restrict__ out) {
    int w = (blockIdx.x * blockDim.x + threadIdx.x) >> 5;
    int lane = threadIdx.x & 31;
    if (w >= NNODES) return;

    const float* zr = g_zB + (size_t)w * NC;
    float v0 = zr[lane];
    float v1 = (lane < 8) ? zr[32 + lane] : -3.4e38f;

    float m = fmaxf(v0, v1);
    #pragma unroll
    for (int off = 16; off > 0; off >>= 1)
        m = fmaxf(m, __shfl_xor_sync(0xffffffff, m, off));

    float s = __expf(v0 - m) + ((lane < 8) ? __expf(v1 - m) : 0.0f);
    #pragma unroll
    for (int off = 16; off > 0; off >>= 1)
        s += __shfl_xor_sync(0xffffffff, s, off);

    float lse = m + logf(s);
    float* o = out + (size_t)w * NC;
    o[lane] = v0 - lse;
    if (lane < 8) o[32 + lane] = v1 - lse;
}

// ---------------- launch ----------------
extern "C" void kernel_launch(void* const* d_in, const int* in_sizes, int n_in,
                              void* d_out, int out_size) {
    const float* x  = (const float*)d_in[0];
    const float* W1 = (const float*)d_in[1];
    const float* b1 = (const float*)d_in[2];
    const float* W2 = (const float*)d_in[3];
    const float* b2 = (const float*)d_in[4];
    const int*   ei = (const int*)d_in[5];
    float* out = (float*)d_out;
    int E = in_sizes[5] / 2;

    // graph preprocessing -> CSR + normalized weights
    zero_deg_kernel<<<(NNODES + 255) / 256, 256>>>();
    count_deg_kernel<<<(E + 255) / 256, 256>>>(ei, E);
    scan_kernel<<<1, 1024>>>(E);
    scatter_kernel<<<(E + 255) / 256, 256>>>(ei, E);

    // bf16 split conversion for tensor-core gemm1
    convert_x_kernel<<<(NNODES * FIN / 4 + 255) / 256, 256>>>(x);
    convert_w_kernel<<<(FIN * HID + 255) / 256, 256>>>(W1);

    // MLP encoder (gemm1: BN = full HID -> A streamed exactly once)
    gemm1_mma_kernel<<<(NNODES + 127) / 128, 512>>>(b1);
    gemm2_kernel<<<(NNODES + 63) / 64, 256>>>(W2, b2);

    // K=10 APPNP steps; src: 0=h 1=zA 2=zB, dst: 1=zA 2=zB
    int spmmGrid = (NNODES * 32 + 255) / 256;
    for (int i = 1; i <= KSTEPS; i++) {
        int src = (i == 1) ? 0 : ((i & 1) ? 2 : 1);
        int dst = (i & 1) ? 1 : 2;
        spmm_kernel<<<spmmGrid, 256>>>(src, dst);
    }

    // final z is in g_zB (K even)
    logsoftmax_kernel<<<spmmGrid, 256>>>(out);
}

// round 9
// speedup vs baseline: 1.5480x; 1.0136x over previous
#include <cuda_runtime.h>
#include <cuda_bf16.h>
#include <math.h>

#define NNODES 100000
#define FIN    512
#define HID    256
#define NC     40
#define KSTEPS 10
#define EMAX   3200000
#define ALPHA  0.1f

// ---------------- device scratch (no allocations allowed) ----------------
__device__ float g_hid[NNODES * HID];      // ~102 MB
__device__ float g_h  [NNODES * NC];       // 16 MB
__device__ float g_zA [NNODES * NC];
__device__ float g_zB [NNODES * NC];
__device__ float g_dinv[NNODES];
__device__ int   g_deg [NNODES];
__device__ int   g_rowptr[NNODES + 1];
__device__ int   g_fill[NNODES];
__device__ int2  g_edge[EMAX];             // (col, ew bits) packed

// bf16 split W for tensor-core gemm1 (x is converted in-kernel)
__device__ __nv_bfloat16 g_whT[HID * FIN];      // [n][k]
__device__ __nv_bfloat16 g_wlT[HID * FIN];

// ---------------- graph preprocessing ----------------
__global__ void zero_deg_kernel() {
    int i = blockIdx.x * blockDim.x + threadIdx.x;
    if (i < NNODES) g_deg[i] = 0;
}

__global__ void count_deg_kernel(const int* __restrict__ ei, int E) {
    int e = blockIdx.x * blockDim.x + threadIdx.x;
    if (e < E) atomicAdd(&g_deg[ei[e]], 1);
}

__global__ void scan_kernel(int E) {
    const int T = 1024;
    const int CH = (NNODES + T - 1) / T;
    int t = threadIdx.x;
    int beg = t * CH;
    int end = beg + CH; if (end > NNODES) end = NNODES;
    if (beg > NNODES) beg = NNODES;

    int sum = 0;
    for (int i = beg; i < end; i++) sum += g_deg[i];

    __shared__ int sh[1024];
    sh[t] = sum;
    __syncthreads();
    for (int off = 1; off < T; off <<= 1) {
        int v = (t >= off) ? sh[t - off] : 0;
        __syncthreads();
        sh[t] += v;
        __syncthreads();
    }
    int offset = sh[t] - sum;

    int running = offset;
    for (int i = beg; i < end; i++) {
        g_rowptr[i] = running;
        g_fill[i]   = running;
        g_dinv[i]   = rsqrtf((float)(g_deg[i] + 1));   // +1 self-loop
        running += g_deg[i];
    }
    if (t == T - 1) g_rowptr[NNODES] = sh[T - 1];
}

__global__ void scatter_kernel(const int* __restrict__ ei, int E) {
    int e = blockIdx.x * blockDim.x + threadIdx.x;
    if (e >= E) return;
    int r = ei[e];          // destination
    int c = ei[E + e];      // source
    int pos = atomicAdd(&g_fill[r], 1);
    g_edge[pos] = make_int2(c, __float_as_int(g_dinv[r] * g_dinv[c]));
}

// ---------------- W bf16 split conversion (tiny: 0.5 MB) ----------------
__global__ void convert_w_kernel(const float* __restrict__ W1) {
    int i = blockIdx.x * blockDim.x + threadIdx.x;     // over FIN*HID
    if (i >= FIN * HID) return;
    int k = i / HID, n = i - k * HID;
    float v = W1[i];
    __nv_bfloat16 h = __float2bfloat16(v);
    g_whT[n * FIN + k] = h;
    g_wlT[n * FIN + k] = __float2bfloat16(v - __bfloat162float(h));
}

// ---------------- helpers for mma path ----------------
__device__ __forceinline__ unsigned smem_u32(const void* p) {
    return (unsigned)__cvta_generic_to_shared(p);
}
__device__ __forceinline__ void cpasync16(unsigned saddr, const void* gaddr) {
    asm volatile("cp.async.cg.shared.global [%0], [%1], 16;\n" :: "r"(saddr), "l"(gaddr));
}
__device__ __forceinline__ void ldmatrix_x4(unsigned* r, unsigned addr) {
    asm volatile("ldmatrix.sync.aligned.m8n8.x4.shared.b16 {%0,%1,%2,%3}, [%4];\n"
                 : "=r"(r[0]), "=r"(r[1]), "=r"(r[2]), "=r"(r[3]) : "r"(addr));
}
__device__ __forceinline__ void mma_bf16(float* d, const unsigned* a, const unsigned* b) {
    asm volatile("mma.sync.aligned.m16n8k16.row.col.f32.bf16.bf16.f32 "
                 "{%0,%1,%2,%3}, {%4,%5,%6,%7}, {%8,%9}, {%0,%1,%2,%3};\n"
                 : "+f"(d[0]), "+f"(d[1]), "+f"(d[2]), "+f"(d[3])
                 : "r"(a[0]), "r"(a[1]), "r"(a[2]), "r"(a[3]), "r"(b[0]), "r"(b[1]));
}
__device__ __forceinline__ unsigned pack_bf16x2(__nv_bfloat16 lo, __nv_bfloat16 hi) {
    unsigned short ul = *(unsigned short*)&lo, uh = *(unsigned short*)&hi;
    return (unsigned)ul | ((unsigned)uh << 16);
}

// swizzled offset within [rows x 16] bf16 tile (32B rows, 2 x 16B chunks).
// chunk ^= (r>>2)&1  -> conflict-free for all ldmatrix 8-row phases.
__device__ __forceinline__ unsigned swz16(int r, int ch) {
    return (unsigned)(r * 32 + ((ch ^ ((r >> 2) & 1)) << 4));
}

// ---------------- GEMM1, fused convert + bf16-split, via tensor cores --------------
// h1 = relu(x@W1 + b1) ~= relu(ah@wh + al@wh + ah@wl + b1)
// BM=128 BN=256(full HID) BK=16 (32 chunks x 3 passes), 512 threads (16 warps, 4m x 4n)
#define NCHUNK 32

__global__ __launch_bounds__(512) void gemm1_fused_kernel(
    const float* __restrict__ X, const float* __restrict__ b1)
{
    __shared__ __nv_bfloat16 sAh[2][128 * 16];   // 4KB each
    __shared__ __nv_bfloat16 sAl[2][128 * 16];   // 4KB each
    __shared__ __nv_bfloat16 sWh[2][256 * 16];   // 8KB each
    __shared__ __nv_bfloat16 sWl[2][256 * 16];   // 8KB each  (total 48KB)

    const int tid  = threadIdx.x;
    const int lane = tid & 31;
    const int wid  = tid >> 5;
    const int wm   = wid & 3;     // 4 warps along M (32 rows each)
    const int wn   = wid >> 2;    // 4 warps along N (64 cols each)
    const int m0 = blockIdx.x * 128;

    // per-thread A load/store coords: row = tid>>2, 4 k-floats at (tid&3)*4
    const int ar  = tid >> 2;
    const int ac4 = (tid & 3) * 4;
    int arow = m0 + ar; if (arow > NNODES - 1) arow = NNODES - 1;
    const float* xsrc = X + (size_t)arow * FIN + ac4;
    const unsigned stsOff = swz16(ar, ac4 >> 3) + (ac4 & 4) * 2;  // +8B for odd half

    // W load coords: row = tid>>1 (0..255), chunk = tid&1
    const int wr  = tid >> 1;
    const int wch = tid & 1;
    const unsigned wOff = swz16(wr, wch);
    const __nv_bfloat16* whsrc = g_whT + (size_t)wr * FIN + wch * 8;
    const __nv_bfloat16* wlsrc = g_wlT + (size_t)wr * FIN + wch * 8;

    float acc[2][8][4];
    #pragma unroll
    for (int mf = 0; mf < 2; mf++)
        #pragma unroll
        for (int nf = 0; nf < 8; nf++)
            #pragma unroll
            for (int q = 0; q < 4; q++) acc[mf][nf][q] = 0.0f;

    // prologue: chunk 0
    float4 xcur = *(const float4*)xsrc;
    {
        cpasync16(smem_u32(sWh[0]) + wOff, whsrc);
        cpasync16(smem_u32(sWl[0]) + wOff, wlsrc);
        asm volatile("cp.async.commit_group;\n" ::);
    }

    for (int i = 0; i < NCHUNK; i++) {
        const int buf = i & 1;
        float4 xnext;
        if (i + 1 < NCHUNK) {
            xnext = *(const float4*)(xsrc + (i + 1) * 16);
            cpasync16(smem_u32(sWh[buf ^ 1]) + wOff, whsrc + (i + 1) * 16);
            cpasync16(smem_u32(sWl[buf ^ 1]) + wOff, wlsrc + (i + 1) * 16);
            asm volatile("cp.async.commit_group;\n" ::);
            asm volatile("cp.async.wait_group 1;\n" ::);
        } else {
            asm volatile("cp.async.wait_group 0;\n" ::);
        }

        // convert xcur -> ah/al and store (8B each)
        {
            __nv_bfloat16 h0 = __float2bfloat16(xcur.x);
            __nv_bfloat16 h1 = __float2bfloat16(xcur.y);
            __nv_bfloat16 h2 = __float2bfloat16(xcur.z);
            __nv_bfloat16 h3 = __float2bfloat16(xcur.w);
            uint2 vh = make_uint2(pack_bf16x2(h0, h1), pack_bf16x2(h2, h3));
            __nv_bfloat16 l0 = __float2bfloat16(xcur.x - __bfloat162float(h0));
            __nv_bfloat16 l1 = __float2bfloat16(xcur.y - __bfloat162float(h1));
            __nv_bfloat16 l2 = __float2bfloat16(xcur.z - __bfloat162float(h2));
            __nv_bfloat16 l3 = __float2bfloat16(xcur.w - __bfloat162float(h3));
            uint2 vl = make_uint2(pack_bf16x2(l0, l1), pack_bf16x2(l2, l3));
            *(uint2*)((char*)sAh[buf] + stsOff) = vh;
            *(uint2*)((char*)sAl[buf] + stsOff) = vl;
        }
        __syncthreads();

        // compute chunk: 3 passes sharing tiles
        {
            const unsigned ahb = smem_u32(sAh[buf]);
            const unsigned alb = smem_u32(sAl[buf]);
            const unsigned whb = smem_u32(sWh[buf]);
            const unsigned wlb = smem_u32(sWl[buf]);

            unsigned fwh[8][2];
            #pragma unroll
            for (int np = 0; np < 4; np++) {
                int mat = lane >> 3, rr = lane & 7;
                int n  = wn * 64 + np * 16 + (mat >> 1) * 8 + rr;
                int ch = mat & 1;
                unsigned t[4];
                ldmatrix_x4(t, whb + swz16(n, ch));
                fwh[np * 2][0] = t[0];     fwh[np * 2][1] = t[1];
                fwh[np * 2 + 1][0] = t[2]; fwh[np * 2 + 1][1] = t[3];
            }
            unsigned fal[2][4];
            #pragma unroll
            for (int mf = 0; mf < 2; mf++) {
                int row = wm * 32 + mf * 16 + (lane & 15);
                ldmatrix_x4(fal[mf], alb + swz16(row, lane >> 4));
            }
            #pragma unroll
            for (int mf = 0; mf < 2; mf++)
                #pragma unroll
                for (int nf = 0; nf < 8; nf++)
                    mma_bf16(acc[mf][nf], fal[mf], fwh[nf]);

            unsigned fah[2][4];
            #pragma unroll
            for (int mf = 0; mf < 2; mf++) {
                int row = wm * 32 + mf * 16 + (lane & 15);
                ldmatrix_x4(fah[mf], ahb + swz16(row, lane >> 4));
            }
            #pragma unroll
            for (int mf = 0; mf < 2; mf++)
                #pragma unroll
                for (int nf = 0; nf < 8; nf++)
                    mma_bf16(acc[mf][nf], fah[mf], fwh[nf]);

            unsigned fwl[8][2];
            #pragma unroll
            for (int np = 0; np < 4; np++) {
                int mat = lane >> 3, rr = lane & 7;
                int n  = wn * 64 + np * 16 + (mat >> 1) * 8 + rr;
                int ch = mat & 1;
                unsigned t[4];
                ldmatrix_x4(t, wlb + swz16(n, ch));
                fwl[np * 2][0] = t[0];     fwl[np * 2][1] = t[1];
                fwl[np * 2 + 1][0] = t[2]; fwl[np * 2 + 1][1] = t[3];
            }
            #pragma unroll
            for (int mf = 0; mf < 2; mf++)
                #pragma unroll
                for (int nf = 0; nf < 8; nf++)
                    mma_bf16(acc[mf][nf], fah[mf], fwl[nf]);
        }
        __syncthreads();
        xcur = xnext;
    }

    // epilogue: relu(acc + bias) -> g_hid fp32
    const int g  = lane >> 2;          // accum row within 8
    const int c2 = (lane & 3) * 2;     // accum col pair
    #pragma unroll
    for (int mf = 0; mf < 2; mf++) {
        #pragma unroll
        for (int nf = 0; nf < 8; nf++) {
            int n = wn * 64 + nf * 8 + c2;
            float bn0 = b1[n], bn1 = b1[n + 1];
            int m_lo = m0 + wm * 32 + mf * 16 + g;
            int m_hi = m_lo + 8;
            if (m_lo < NNODES) {
                float2 v = make_float2(fmaxf(acc[mf][nf][0] + bn0, 0.0f),
                                       fmaxf(acc[mf][nf][1] + bn1, 0.0f));
                *(float2*)&g_hid[(size_t)m_lo * HID + n] = v;
            }
            if (m_hi < NNODES) {
                float2 v = make_float2(fmaxf(acc[mf][nf][2] + bn0, 0.0f),
                                       fmaxf(acc[mf][nf][3] + bn1, 0.0f));
                *(float2*)&g_hid[(size_t)m_hi * HID + n] = v;
            }
        }
    }
}

// ---------------- GEMM2: h = hid @ W2 + b2  [100000,256]x[256,40] ----------------
__global__ __launch_bounds__(256) void gemm2_kernel(
    const float* __restrict__ W2, const float* __restrict__ b2)
{
    __shared__ float Hs[32][65];
    __shared__ float Ws[32][40];

    int tid = threadIdx.x;
    int m0 = blockIdx.x * 64;
    int tx = tid & 7;        // 8 -> 5 cols each
    int ty = tid >> 3;       // 32 -> 2 rows each

    float acc[2][5];
    #pragma unroll
    for (int r = 0; r < 2; r++)
        #pragma unroll
        for (int j = 0; j < 5; j++) acc[r][j] = 0.0f;

    for (int k0 = 0; k0 < HID; k0 += 32) {
        {
            int kk = tid & 31;
            int mb = tid >> 5;   // 0..7
            #pragma unroll
            for (int mi = 0; mi < 8; mi++) {
                int m = mi * 8 + mb;
                float v = 0.0f;
                if (m0 + m < NNODES)
                    v = g_hid[(size_t)(m0 + m) * HID + k0 + kk];
                Hs[kk][m] = v;
            }
        }
        #pragma unroll
        for (int l = 0; l < 5; l++) {
            int idx = tid + l * 256;
            int kr = idx / 40;
            int n = idx - kr * 40;
            Ws[kr][n] = W2[(size_t)(k0 + kr) * NC + n];
        }
        __syncthreads();

        #pragma unroll
        for (int k = 0; k < 32; k++) {
            float a0 = Hs[k][ty * 2];
            float a1 = Hs[k][ty * 2 + 1];
            #pragma unroll
            for (int j = 0; j < 5; j++) {
                float b = Ws[k][tx * 5 + j];
                acc[0][j] += a0 * b;
                acc[1][j] += a1 * b;
            }
        }
        __syncthreads();
    }

    #pragma unroll
    for (int r = 0; r < 2; r++) {
        int m = m0 + ty * 2 + r;
        if (m < NNODES) {
            #pragma unroll
            for (int j = 0; j < 5; j++) {
                int n = tx * 5 + j;
                g_h[(size_t)m * NC + n] = acc[r][j] + b2[n];
            }
        }
    }
}

// ---------------- APPNP propagation step: zout = 0.9*A_norm*zin + 0.1*h ----------------
// warp per row; 3 edge sub-groups of 10 lanes, each lane owns one float4 (4 channels)
__global__ __launch_bounds__(256) void spmm_kernel(int srcSel, int dstSel) {
    const float* zin  = (srcSel == 0) ? g_h : (srcSel == 1 ? g_zA : g_zB);
    float*       zout = (dstSel == 1) ? g_zA : g_zB;

    int w = (blockIdx.x * blockDim.x + threadIdx.x) >> 5;
    int lane = threadIdx.x & 31;
    if (w >= NNODES) return;
    int s = g_rowptr[w];
    int e = g_rowptr[w + 1];

    int sub = lane / 10;          // 0..2 active, 3 for lanes 30,31 (idle)
    int cg  = lane - sub * 10;    // channel group 0..9 -> channels cg*4..cg*4+3

    float4 acc = make_float4(0.f, 0.f, 0.f, 0.f);
    if (sub < 3) {
        for (int j = s + sub; j < e; j += 3) {
            int2 ed = __ldg(&g_edge[j]);
            float wt = __int_as_float(ed.y);
            float4 zv = *(const float4*)(zin + (size_t)ed.x * NC + cg * 4);
            acc.x += wt * zv.x;
            acc.y += wt * zv.y;
            acc.z += wt * zv.z;
            acc.w += wt * zv.w;
        }
    }

    // reduce the 3 sub-group partials: lane l (<10) needs l, l+10, l+20.
    float tx1 = __shfl_down_sync(0xffffffff, acc.x, 10);
    float ty1 = __shfl_down_sync(0xffffffff, acc.y, 10);
    float tz1 = __shfl_down_sync(0xffffffff, acc.z, 10);
    float tw1 = __shfl_down_sync(0xffffffff, acc.w, 10);
    float tx2 = __shfl_down_sync(0xffffffff, acc.x, 20);
    float ty2 = __shfl_down_sync(0xffffffff, acc.y, 20);
    float tz2 = __shfl_down_sync(0xffffffff, acc.z, 20);
    float tw2 = __shfl_down_sync(0xffffffff, acc.w, 20);

    if (lane < 10) {
        acc.x += tx1 + tx2;
        acc.y += ty1 + ty2;
        acc.z += tz1 + tz2;
        acc.w += tw1 + tw2;

        // self loop
        float dv = g_dinv[w];
        float ws = dv * dv;
        float4 zr = *(const float4*)(zin + (size_t)w * NC + cg * 4);
        acc.x += ws * zr.x;
        acc.y += ws * zr.y;
        acc.z += ws * zr.z;
        acc.w += ws * zr.w;

        float4 hr = *(const float4*)(g_h + (size_t)w * NC + cg * 4);
        float4 o;
        o.x = (1.0f - ALPHA) * acc.x + ALPHA * hr.x;
        o.y = (1.0f - ALPHA) * acc.y + ALPHA * hr.y;
        o.z = (1.0f - ALPHA) * acc.z + ALPHA * hr.z;
        o.w = (1.0f - ALPHA) * acc.w + ALPHA * hr.w;
        *(float4*)(zout + (size_t)w * NC + cg * 4) = o;
    }
}

// ---------------- log_softmax over 40 classes, warp per row ----------------
__global__ __launch_bounds__(256) void logsoftmax_kernel(float* __restrict__ out) {
    int w = (blockIdx.x * blockDim.x + threadIdx.x) >> 5;
    int lane = threadIdx.x & 31;
    if (w >= NNODES) return;

    const float* zr = g_zB + (size_t)w * NC;
    float v0 = zr[lane];
    float v1 = (lane < 8) ? zr[32 + lane] : -3.4e38f;

    float m = fmaxf(v0, v1);
    #pragma unroll
    for (int off = 16; off > 0; off >>= 1)
        m = fmaxf(m, __shfl_xor_sync(0xffffffff, m, off));

    float s = __expf(v0 - m) + ((lane < 8) ? __expf(v1 - m) : 0.0f);
    #pragma unroll
    for (int off = 16; off > 0; off >>= 1)
        s += __shfl_xor_sync(0xffffffff, s, off);

    float lse = m + logf(s);
    float* o = out + (size_t)w * NC;
    o[lane] = v0 - lse;
    if (lane < 8) o[32 + lane] = v1 - lse;
}

// ---------------- launch ----------------
extern "C" void kernel_launch(void* const* d_in, const int* in_sizes, int n_in,
                              void* d_out, int out_size) {
    const float* x  = (const float*)d_in[0];
    const float* W1 = (const float*)d_in[1];
    const float* b1 = (const float*)d_in[2];
    const float* W2 = (const float*)d_in[3];
    const float* b2 = (const float*)d_in[4];
    const int*   ei = (const int*)d_in[5];
    float* out = (float*)d_out;
    int E = in_sizes[5] / 2;

    // graph preprocessing -> CSR + normalized weights
    zero_deg_kernel<<<(NNODES + 255) / 256, 256>>>();
    count_deg_kernel<<<(E + 255) / 256, 256>>>(ei, E);
    scan_kernel<<<1, 1024>>>(E);
    scatter_kernel<<<(E + 255) / 256, 256>>>(ei, E);

    // W bf16 split (x converted inside gemm1)
    convert_w_kernel<<<(FIN * HID + 255) / 256, 256>>>(W1);

    // MLP encoder (gemm1: fused fp32->bf16 split conversion, BN = full HID)
    gemm1_fused_kernel<<<(NNODES + 127) / 128, 512>>>(x, b1);
    gemm2_kernel<<<(NNODES + 63) / 64, 256>>>(W2, b2);

    // K=10 APPNP steps; src: 0=h 1=zA 2=zB, dst: 1=zA 2=zB
    int spmmGrid = (NNODES * 32 + 255) / 256;
    for (int i = 1; i <= KSTEPS; i++) {
        int src = (i == 1) ? 0 : ((i & 1) ? 2 : 1);
        int dst = (i & 1) ? 1 : 2;
        spmm_kernel<<<spmmGrid, 256>>>(src, dst);
    }

    // final z is in g_zB (K even)
    logsoftmax_kernel<<<spmmGrid, 256>>>(out);
}

// round 10
// speedup vs baseline: 1.9965x; 1.2897x over previous
#include <cuda_runtime.h>
#include <cuda_bf16.h>
#include <math.h>

#define NNODES 100000
#define FIN    512
#define HID    256
#define NC     40
#define KSTEPS 10
#define EMAX   3200000
#define ALPHA  0.1f

// ---------------- device scratch (no allocations allowed) ----------------
__device__ float g_hid[NNODES * HID];      // ~102 MB
__device__ float g_h  [NNODES * NC];       // 16 MB
__device__ float g_zA [NNODES * NC];
__device__ float g_zB [NNODES * NC];
__device__ float g_dinv[NNODES];
__device__ int   g_deg [NNODES];
__device__ int   g_rowptr[NNODES + 1];
__device__ int   g_fill[NNODES];
__device__ int2  g_edge[EMAX];             // (col, ew bits) packed

// bf16 split W for tensor-core gemm1 (x is converted in-kernel)
__device__ __nv_bfloat16 g_whT[HID * FIN];      // [n][k]
__device__ __nv_bfloat16 g_wlT[HID * FIN];

// ---------------- graph preprocessing ----------------
__global__ void zero_deg_kernel() {
    int i = blockIdx.x * blockDim.x + threadIdx.x;
    if (i < NNODES) g_deg[i] = 0;
}

__global__ void count_deg_kernel(const int* __restrict__ ei, int E) {
    int e = blockIdx.x * blockDim.x + threadIdx.x;
    if (e < E) atomicAdd(&g_deg[ei[e]], 1);
}

__global__ void scan_kernel(int E) {
    const int T = 1024;
    const int CH = (NNODES + T - 1) / T;
    int t = threadIdx.x;
    int beg = t * CH;
    int end = beg + CH; if (end > NNODES) end = NNODES;
    if (beg > NNODES) beg = NNODES;

    int sum = 0;
    for (int i = beg; i < end; i++) sum += g_deg[i];

    __shared__ int sh[1024];
    sh[t] = sum;
    __syncthreads();
    for (int off = 1; off < T; off <<= 1) {
        int v = (t >= off) ? sh[t - off] : 0;
        __syncthreads();
        sh[t] += v;
        __syncthreads();
    }
    int offset = sh[t] - sum;

    int running = offset;
    for (int i = beg; i < end; i++) {
        g_rowptr[i] = running;
        g_fill[i]   = running;
        g_dinv[i]   = rsqrtf((float)(g_deg[i] + 1));   // +1 self-loop
        running += g_deg[i];
    }
    if (t == T - 1) g_rowptr[NNODES] = sh[T - 1];
}

__global__ void scatter_kernel(const int* __restrict__ ei, int E) {
    int e = blockIdx.x * blockDim.x + threadIdx.x;
    if (e >= E) return;
    int r = ei[e];          // destination
    int c = ei[E + e];      // source
    int pos = atomicAdd(&g_fill[r], 1);
    g_edge[pos] = make_int2(c, __float_as_int(g_dinv[r] * g_dinv[c]));
}

// ---------------- W bf16 split conversion (tiny: 0.5 MB) ----------------
__global__ void convert_w_kernel(const float* __restrict__ W1) {
    int i = blockIdx.x * blockDim.x + threadIdx.x;     // over FIN*HID
    if (i >= FIN * HID) return;
    int k = i / HID, n = i - k * HID;
    float v = W1[i];
    __nv_bfloat16 h = __float2bfloat16(v);
    g_whT[n * FIN + k] = h;
    g_wlT[n * FIN + k] = __float2bfloat16(v - __bfloat162float(h));
}

// ---------------- helpers for mma path ----------------
__device__ __forceinline__ unsigned smem_u32(const void* p) {
    return (unsigned)__cvta_generic_to_shared(p);
}
__device__ __forceinline__ void cpasync16(unsigned saddr, const void* gaddr) {
    asm volatile("cp.async.cg.shared.global [%0], [%1], 16;\n" :: "r"(saddr), "l"(gaddr));
}
__device__ __forceinline__ void ldmatrix_x4(unsigned* r, unsigned addr) {
    asm volatile("ldmatrix.sync.aligned.m8n8.x4.shared.b16 {%0,%1,%2,%3}, [%4];\n"
                 : "=r"(r[0]), "=r"(r[1]), "=r"(r[2]), "=r"(r[3]) : "r"(addr));
}
__device__ __forceinline__ void mma_bf16(float* d, const unsigned* a, const unsigned* b) {
    asm volatile("mma.sync.aligned.m16n8k16.row.col.f32.bf16.bf16.f32 "
                 "{%0,%1,%2,%3}, {%4,%5,%6,%7}, {%8,%9}, {%0,%1,%2,%3};\n"
                 : "+f"(d[0]), "+f"(d[1]), "+f"(d[2]), "+f"(d[3])
                 : "r"(a[0]), "r"(a[1]), "r"(a[2]), "r"(a[3]), "r"(b[0]), "r"(b[1]));
}
__device__ __forceinline__ unsigned pack_bf16x2(__nv_bfloat16 lo, __nv_bfloat16 hi) {
    unsigned short ul = *(unsigned short*)&lo, uh = *(unsigned short*)&hi;
    return (unsigned)ul | ((unsigned)uh << 16);
}

// swizzled offset within [rows x 16] bf16 tile (32B rows, 2 x 16B chunks).
__device__ __forceinline__ unsigned swz16(int r, int ch) {
    return (unsigned)(r * 32 + ((ch ^ ((r >> 2) & 1)) << 4));
}

// ---------------- GEMM1, fused convert + bf16-split, via tensor cores --------------
// h1 = relu(x@W1 + b1) ~= relu(ah@wh + al@wh + ah@wl + b1)
// BM=128 BN=256(full HID) BK=16 (32 chunks x 3 passes), 512 threads (16 warps, 4m x 4n)
#define NCHUNK 32

__global__ __launch_bounds__(512) void gemm1_fused_kernel(
    const float* __restrict__ X, const float* __restrict__ b1)
{
    __shared__ __nv_bfloat16 sAh[2][128 * 16];   // 4KB each
    __shared__ __nv_bfloat16 sAl[2][128 * 16];   // 4KB each
    __shared__ __nv_bfloat16 sWh[2][256 * 16];   // 8KB each
    __shared__ __nv_bfloat16 sWl[2][256 * 16];   // 8KB each  (total 48KB)

    const int tid  = threadIdx.x;
    const int lane = tid & 31;
    const int wid  = tid >> 5;
    const int wm   = wid & 3;     // 4 warps along M (32 rows each)
    const int wn   = wid >> 2;    // 4 warps along N (64 cols each)
    const int m0 = blockIdx.x * 128;

    // per-thread A load/store coords: row = tid>>2, 4 k-floats at (tid&3)*4
    const int ar  = tid >> 2;
    const int ac4 = (tid & 3) * 4;
    int arow = m0 + ar; if (arow > NNODES - 1) arow = NNODES - 1;
    const float* xsrc = X + (size_t)arow * FIN + ac4;
    const unsigned stsOff = swz16(ar, ac4 >> 3) + (ac4 & 4) * 2;  // +8B for odd half

    // W load coords: row = tid>>1 (0..255), chunk = tid&1
    const int wr  = tid >> 1;
    const int wch = tid & 1;
    const unsigned wOff = swz16(wr, wch);
    const __nv_bfloat16* whsrc = g_whT + (size_t)wr * FIN + wch * 8;
    const __nv_bfloat16* wlsrc = g_wlT + (size_t)wr * FIN + wch * 8;

    float acc[2][8][4];
    #pragma unroll
    for (int mf = 0; mf < 2; mf++)
        #pragma unroll
        for (int nf = 0; nf < 8; nf++)
            #pragma unroll
            for (int q = 0; q < 4; q++) acc[mf][nf][q] = 0.0f;

    // prologue: chunk 0
    float4 xcur = *(const float4*)xsrc;
    {
        cpasync16(smem_u32(sWh[0]) + wOff, whsrc);
        cpasync16(smem_u32(sWl[0]) + wOff, wlsrc);
        asm volatile("cp.async.commit_group;\n" ::);
    }

    for (int i = 0; i < NCHUNK; i++) {
        const int buf = i & 1;
        float4 xnext;
        if (i + 1 < NCHUNK) {
            xnext = *(const float4*)(xsrc + (i + 1) * 16);
            cpasync16(smem_u32(sWh[buf ^ 1]) + wOff, whsrc + (i + 1) * 16);
            cpasync16(smem_u32(sWl[buf ^ 1]) + wOff, wlsrc + (i + 1) * 16);
            asm volatile("cp.async.commit_group;\n" ::);
            asm volatile("cp.async.wait_group 1;\n" ::);
        } else {
            asm volatile("cp.async.wait_group 0;\n" ::);
        }

        // convert xcur -> ah/al and store (8B each)
        {
            __nv_bfloat16 h0 = __float2bfloat16(xcur.x);
            __nv_bfloat16 h1 = __float2bfloat16(xcur.y);
            __nv_bfloat16 h2 = __float2bfloat16(xcur.z);
            __nv_bfloat16 h3 = __float2bfloat16(xcur.w);
            uint2 vh = make_uint2(pack_bf16x2(h0, h1), pack_bf16x2(h2, h3));
            __nv_bfloat16 l0 = __float2bfloat16(xcur.x - __bfloat162float(h0));
            __nv_bfloat16 l1 = __float2bfloat16(xcur.y - __bfloat162float(h1));
            __nv_bfloat16 l2 = __float2bfloat16(xcur.z - __bfloat162float(h2));
            __nv_bfloat16 l3 = __float2bfloat16(xcur.w - __bfloat162float(h3));
            uint2 vl = make_uint2(pack_bf16x2(l0, l1), pack_bf16x2(l2, l3));
            *(uint2*)((char*)sAh[buf] + stsOff) = vh;
            *(uint2*)((char*)sAl[buf] + stsOff) = vl;
        }
        __syncthreads();

        // compute chunk: 3 passes sharing tiles
        {
            const unsigned ahb = smem_u32(sAh[buf]);
            const unsigned alb = smem_u32(sAl[buf]);
            const unsigned whb = smem_u32(sWh[buf]);
            const unsigned wlb = smem_u32(sWl[buf]);

            unsigned fwh[8][2];
            #pragma unroll
            for (int np = 0; np < 4; np++) {
                int mat = lane >> 3, rr = lane & 7;
                int n  = wn * 64 + np * 16 + (mat >> 1) * 8 + rr;
                int ch = mat & 1;
                unsigned t[4];
                ldmatrix_x4(t, whb + swz16(n, ch));
                fwh[np * 2][0] = t[0];     fwh[np * 2][1] = t[1];
                fwh[np * 2 + 1][0] = t[2]; fwh[np * 2 + 1][1] = t[3];
            }
            unsigned fal[2][4];
            #pragma unroll
            for (int mf = 0; mf < 2; mf++) {
                int row = wm * 32 + mf * 16 + (lane & 15);
                ldmatrix_x4(fal[mf], alb + swz16(row, lane >> 4));
            }
            #pragma unroll
            for (int mf = 0; mf < 2; mf++)
                #pragma unroll
                for (int nf = 0; nf < 8; nf++)
                    mma_bf16(acc[mf][nf], fal[mf], fwh[nf]);

            unsigned fah[2][4];
            #pragma unroll
            for (int mf = 0; mf < 2; mf++) {
                int row = wm * 32 + mf * 16 + (lane & 15);
                ldmatrix_x4(fah[mf], ahb + swz16(row, lane >> 4));
            }
            #pragma unroll
            for (int mf = 0; mf < 2; mf++)
                #pragma unroll
                for (int nf = 0; nf < 8; nf++)
                    mma_bf16(acc[mf][nf], fah[mf], fwh[nf]);

            unsigned fwl[8][2];
            #pragma unroll
            for (int np = 0; np < 4; np++) {
                int mat = lane >> 3, rr = lane & 7;
                int n  = wn * 64 + np * 16 + (mat >> 1) * 8 + rr;
                int ch = mat & 1;
                unsigned t[4];
                ldmatrix_x4(t, wlb + swz16(n, ch));
                fwl[np * 2][0] = t[0];     fwl[np * 2][1] = t[1];
                fwl[np * 2 + 1][0] = t[2]; fwl[np * 2 + 1][1] = t[3];
            }
            #pragma unroll
            for (int mf = 0; mf < 2; mf++)
                #pragma unroll
                for (int nf = 0; nf < 8; nf++)
                    mma_bf16(acc[mf][nf], fah[mf], fwl[nf]);
        }
        __syncthreads();
        xcur = xnext;
    }

    // epilogue: relu(acc + bias) -> g_hid fp32
    const int g  = lane >> 2;          // accum row within 8
    const int c2 = (lane & 3) * 2;     // accum col pair
    #pragma unroll
    for (int mf = 0; mf < 2; mf++) {
        #pragma unroll
        for (int nf = 0; nf < 8; nf++) {
            int n = wn * 64 + nf * 8 + c2;
            float bn0 = b1[n], bn1 = b1[n + 1];
            int m_lo = m0 + wm * 32 + mf * 16 + g;
            int m_hi = m_lo + 8;
            if (m_lo < NNODES) {
                float2 v = make_float2(fmaxf(acc[mf][nf][0] + bn0, 0.0f),
                                       fmaxf(acc[mf][nf][1] + bn1, 0.0f));
                *(float2*)&g_hid[(size_t)m_lo * HID + n] = v;
            }
            if (m_hi < NNODES) {
                float2 v = make_float2(fmaxf(acc[mf][nf][2] + bn0, 0.0f),
                                       fmaxf(acc[mf][nf][3] + bn1, 0.0f));
                *(float2*)&g_hid[(size_t)m_hi * HID + n] = v;
            }
        }
    }
}

// ---------------- GEMM2: h = hid @ W2 + b2  [100000,256]x[256,40] ----------------
__global__ __launch_bounds__(256) void gemm2_kernel(
    const float* __restrict__ W2, const float* __restrict__ b2)
{
    __shared__ float Hs[32][65];
    __shared__ float Ws[32][40];

    int tid = threadIdx.x;
    int m0 = blockIdx.x * 64;
    int tx = tid & 7;        // 8 -> 5 cols each
    int ty = tid >> 3;       // 32 -> 2 rows each

    float acc[2][5];
    #pragma unroll
    for (int r = 0; r < 2; r++)
        #pragma unroll
        for (int j = 0; j < 5; j++) acc[r][j] = 0.0f;

    for (int k0 = 0; k0 < HID; k0 += 32) {
        {
            int kk = tid & 31;
            int mb = tid >> 5;   // 0..7
            #pragma unroll
            for (int mi = 0; mi < 8; mi++) {
                int m = mi * 8 + mb;
                float v = 0.0f;
                if (m0 + m < NNODES)
                    v = g_hid[(size_t)(m0 + m) * HID + k0 + kk];
                Hs[kk][m] = v;
            }
        }
        #pragma unroll
        for (int l = 0; l < 5; l++) {
            int idx = tid + l * 256;
            int kr = idx / 40;
            int n = idx - kr * 40;
            Ws[kr][n] = W2[(size_t)(k0 + kr) * NC + n];
        }
        __syncthreads();

        #pragma unroll
        for (int k = 0; k < 32; k++) {
            float a0 = Hs[k][ty * 2];
            float a1 = Hs[k][ty * 2 + 1];
            #pragma unroll
            for (int j = 0; j < 5; j++) {
                float b = Ws[k][tx * 5 + j];
                acc[0][j] += a0 * b;
                acc[1][j] += a1 * b;
            }
        }
        __syncthreads();
    }

    #pragma unroll
    for (int r = 0; r < 2; r++) {
        int m = m0 + ty * 2 + r;
        if (m < NNODES) {
            #pragma unroll
            for (int j = 0; j < 5; j++) {
                int n = tx * 5 + j;
                g_h[(size_t)m * NC + n] = acc[r][j] + b2[n];
            }
        }
    }
}

// ---------------- APPNP propagation step: zout = 0.9*A_norm*zin + 0.1*h ----------------
// warp per row; 3 edge sub-groups of 10 lanes, each lane owns one float4 (4 channels)
__global__ __launch_bounds__(256) void spmm_kernel(int srcSel, int dstSel) {
    const float* zin  = (srcSel == 0) ? g_h : (srcSel == 1 ? g_zA : g_zB);
    float*       zout = (dstSel == 1) ? g_zA : g_zB;

    int w = (blockIdx.x * blockDim.x + threadIdx.x) >> 5;
    int lane = threadIdx.x & 31;
    if (w >= NNODES) return;
    int s = g_rowptr[w];
    int e = g_rowptr[w + 1];

    int sub = lane / 10;          // 0..2 active, 3 for lanes 30,31 (idle)
    int cg  = lane - sub * 10;    // channel group 0..9 -> channels cg*4..cg*4+3

    float4 acc = make_float4(0.f, 0.f, 0.f, 0.f);
    if (sub < 3) {
        for (int j = s + sub; j < e; j += 3) {
            int2 ed = __ldg(&g_edge[j]);
            float wt = __int_as_float(ed.y);
            float4 zv = *(const float4*)(zin + (size_t)ed.x * NC + cg * 4);
            acc.x += wt * zv.x;
            acc.y += wt * zv.y;
            acc.z += wt * zv.z;
            acc.w += wt * zv.w;
        }
    }

    // reduce the 3 sub-group partials: lane l (<10) needs l, l+10, l+20.
    float tx1 = __shfl_down_sync(0xffffffff, acc.x, 10);
    float ty1 = __shfl_down_sync(0xffffffff, acc.y, 10);
    float tz1 = __shfl_down_sync(0xffffffff, acc.z, 10);
    float tw1 = __shfl_down_sync(0xffffffff, acc.w, 10);
    float tx2 = __shfl_down_sync(0xffffffff, acc.x, 20);
    float ty2 = __shfl_down_sync(0xffffffff, acc.y, 20);
    float tz2 = __shfl_down_sync(0xffffffff, acc.z, 20);
    float tw2 = __shfl_down_sync(0xffffffff, acc.w, 20);

    if (lane < 10) {
        acc.x += tx1 + tx2;
        acc.y += ty1 + ty2;
        acc.z += tz1 + tz2;
        acc.w += tw1 + tw2;

        // self loop
        float dv = g_dinv[w];
        float ws = dv * dv;
        float4 zr = *(const float4*)(zin + (size_t)w * NC + cg * 4);
        acc.x += ws * zr.x;
        acc.y += ws * zr.y;
        acc.z += ws * zr.z;
        acc.w += ws * zr.w;

        float4 hr = *(const float4*)(g_h + (size_t)w * NC + cg * 4);
        float4 o;
        o.x = (1.0f - ALPHA) * acc.x + ALPHA * hr.x;
        o.y = (1.0f - ALPHA) * acc.y + ALPHA * hr.y;
        o.z = (1.0f - ALPHA) * acc.z + ALPHA * hr.z;
        o.w = (1.0f - ALPHA) * acc.w + ALPHA * hr.w;
        *(float4*)(zout + (size_t)w * NC + cg * 4) = o;
    }
}

// ---------------- log_softmax over 40 classes, warp per row ----------------
__global__ __launch_bounds__(256) void logsoftmax_kernel(float* __restrict__ out) {
    int w = (blockIdx.x * blockDim.x + threadIdx.x) >> 5;
    int lane = threadIdx.x & 31;
    if (w >= NNODES) return;

    const float* zr = g_zB + (size_t)w * NC;
    float v0 = zr[lane];
    float v1 = (lane < 8) ? zr[32 + lane] : -3.4e38f;

    float m = fmaxf(v0, v1);
    #pragma unroll
    for (int off = 16; off > 0; off >>= 1)
        m = fmaxf(m, __shfl_xor_sync(0xffffffff, m, off));

    float s = __expf(v0 - m) + ((lane < 8) ? __expf(v1 - m) : 0.0f);
    #pragma unroll
    for (int off = 16; off > 0; off >>= 1)
        s += __shfl_xor_sync(0xffffffff, s, off);

    float lse = m + logf(s);
    float* o = out + (size_t)w * NC;
    o[lane] = v0 - lse;
    if (lane < 8) o[32 + lane] = v1 - lse;
}

// ---------------- launch ----------------
extern "C" void kernel_launch(void* const* d_in, const int* in_sizes, int n_in,
                              void* d_out, int out_size) {
    const float* x  = (const float*)d_in[0];
    const float* W1 = (const float*)d_in[1];
    const float* b1 = (const float*)d_in[2];
    const float* W2 = (const float*)d_in[3];
    const float* b2 = (const float*)d_in[4];
    const int*   ei = (const int*)d_in[5];
    float* out = (float*)d_out;
    int E = in_sizes[5] / 2;

    // side stream for graph preprocessing (independent of MLP until spmm).
    // handles created once; captured work is identical on every call.
    static cudaStream_t s2 = nullptr;
    static cudaEvent_t evFork = nullptr, evJoin = nullptr;
    if (s2 == nullptr) {
        cudaStreamCreateWithFlags(&s2, cudaStreamNonBlocking);
        cudaEventCreateWithFlags(&evFork, cudaEventDisableTiming);
        cudaEventCreateWithFlags(&evJoin, cudaEventDisableTiming);
    }

    // fork: s2 depends on everything enqueued so far on the main stream
    cudaEventRecord(evFork, 0);
    cudaStreamWaitEvent(s2, evFork, 0);

    // --- side stream: graph preprocessing -> CSR + normalized weights ---
    zero_deg_kernel<<<(NNODES + 255) / 256, 256, 0, s2>>>();
    count_deg_kernel<<<(E + 255) / 256, 256, 0, s2>>>(ei, E);
    scan_kernel<<<1, 1024, 0, s2>>>(E);
    scatter_kernel<<<(E + 255) / 256, 256, 0, s2>>>(ei, E);
    cudaEventRecord(evJoin, s2);

    // --- main stream: MLP encoder (overlaps with preprocessing) ---
    convert_w_kernel<<<(FIN * HID + 255) / 256, 256>>>(W1);
    gemm1_fused_kernel<<<(NNODES + 127) / 128, 512>>>(x, b1);
    gemm2_kernel<<<(NNODES + 63) / 64, 256>>>(W2, b2);

    // join: spmm needs both g_h (main) and CSR (s2)
    cudaStreamWaitEvent(0, evJoin, 0);

    // K=10 APPNP steps; src: 0=h 1=zA 2=zB, dst: 1=zA 2=zB
    int spmmGrid = (NNODES * 32 + 255) / 256;
    for (int i = 1; i <= KSTEPS; i++) {
        int src = (i == 1) ? 0 : ((i & 1) ? 2 : 1);
        int dst = (i & 1) ? 1 : 2;
        spmm_kernel<<<spmmGrid, 256>>>(src, dst);
    }

    // final z is in g_zB (K even)
    logsoftmax_kernel<<<spmmGrid, 256>>>(out);
}

// round 11
// speedup vs baseline: 2.1517x; 1.0778x over previous
#include <cuda_runtime.h>
#include <cuda_bf16.h>
#include <cuda_fp16.h>
#include <math.h>

#define NNODES 100000
#define FIN    512
#define HID    256
#define NC     40
#define KSTEPS 10
#define EMAX   3200000
#define ALPHA  0.1f

// ---------------- device scratch (no allocations allowed) ----------------
__device__ float g_hid[NNODES * HID];      // ~102 MB
__device__ float g_h  [NNODES * NC];       // 16 MB (fp32 h for injection)
__device__ __half g_h16 [NNODES * NC];     // 8 MB (fp16 h for step-1 gather)
__device__ __half g_z16A[NNODES * NC];     // 8 MB ping
__device__ __half g_z16B[NNODES * NC];     // 8 MB pong
__device__ float g_dinv[NNODES];
__device__ int   g_deg [NNODES];
__device__ int   g_rowptr[NNODES + 1];
__device__ int   g_fill[NNODES];
__device__ int2  g_edge[EMAX];             // (col, ew bits) packed

// bf16 split W for tensor-core gemm1 (x is converted in-kernel)
__device__ __nv_bfloat16 g_whT[HID * FIN];      // [n][k]
__device__ __nv_bfloat16 g_wlT[HID * FIN];

// ---------------- graph preprocessing ----------------
__global__ void zero_deg_kernel() {
    int i = blockIdx.x * blockDim.x + threadIdx.x;
    if (i < NNODES) g_deg[i] = 0;
}

__global__ void count_deg_kernel(const int* __restrict__ ei, int E) {
    int e = blockIdx.x * blockDim.x + threadIdx.x;
    if (e < E) atomicAdd(&g_deg[ei[e]], 1);
}

__global__ void scan_kernel(int E) {
    const int T = 1024;
    const int CH = (NNODES + T - 1) / T;
    int t = threadIdx.x;
    int beg = t * CH;
    int end = beg + CH; if (end > NNODES) end = NNODES;
    if (beg > NNODES) beg = NNODES;

    int sum = 0;
    for (int i = beg; i < end; i++) sum += g_deg[i];

    __shared__ int sh[1024];
    sh[t] = sum;
    __syncthreads();
    for (int off = 1; off < T; off <<= 1) {
        int v = (t >= off) ? sh[t - off] : 0;
        __syncthreads();
        sh[t] += v;
        __syncthreads();
    }
    int offset = sh[t] - sum;

    int running = offset;
    for (int i = beg; i < end; i++) {
        g_rowptr[i] = running;
        g_fill[i]   = running;
        g_dinv[i]   = rsqrtf((float)(g_deg[i] + 1));   // +1 self-loop
        running += g_deg[i];
    }
    if (t == T - 1) g_rowptr[NNODES] = sh[T - 1];
}

__global__ void scatter_kernel(const int* __restrict__ ei, int E) {
    int e = blockIdx.x * blockDim.x + threadIdx.x;
    if (e >= E) return;
    int r = ei[e];          // destination
    int c = ei[E + e];      // source
    int pos = atomicAdd(&g_fill[r], 1);
    g_edge[pos] = make_int2(c, __float_as_int(g_dinv[r] * g_dinv[c]));
}

// ---------------- W bf16 split conversion (tiny: 0.5 MB) ----------------
__global__ void convert_w_kernel(const float* __restrict__ W1) {
    int i = blockIdx.x * blockDim.x + threadIdx.x;     // over FIN*HID
    if (i >= FIN * HID) return;
    int k = i / HID, n = i - k * HID;
    float v = W1[i];
    __nv_bfloat16 h = __float2bfloat16(v);
    g_whT[n * FIN + k] = h;
    g_wlT[n * FIN + k] = __float2bfloat16(v - __bfloat162float(h));
}

// ---------------- helpers for mma path ----------------
__device__ __forceinline__ unsigned smem_u32(const void* p) {
    return (unsigned)__cvta_generic_to_shared(p);
}
__device__ __forceinline__ void cpasync16(unsigned saddr, const void* gaddr) {
    asm volatile("cp.async.cg.shared.global [%0], [%1], 16;\n" :: "r"(saddr), "l"(gaddr));
}
__device__ __forceinline__ void ldmatrix_x4(unsigned* r, unsigned addr) {
    asm volatile("ldmatrix.sync.aligned.m8n8.x4.shared.b16 {%0,%1,%2,%3}, [%4];\n"
                 : "=r"(r[0]), "=r"(r[1]), "=r"(r[2]), "=r"(r[3]) : "r"(addr));
}
__device__ __forceinline__ void mma_bf16(float* d, const unsigned* a, const unsigned* b) {
    asm volatile("mma.sync.aligned.m16n8k16.row.col.f32.bf16.bf16.f32 "
                 "{%0,%1,%2,%3}, {%4,%5,%6,%7}, {%8,%9}, {%0,%1,%2,%3};\n"
                 : "+f"(d[0]), "+f"(d[1]), "+f"(d[2]), "+f"(d[3])
                 : "r"(a[0]), "r"(a[1]), "r"(a[2]), "r"(a[3]), "r"(b[0]), "r"(b[1]));
}
__device__ __forceinline__ unsigned pack_bf16x2(__nv_bfloat16 lo, __nv_bfloat16 hi) {
    unsigned short ul = *(unsigned short*)&lo, uh = *(unsigned short*)&hi;
    return (unsigned)ul | ((unsigned)uh << 16);
}

// swizzled offset within [rows x 16] bf16 tile (32B rows, 2 x 16B chunks).
__device__ __forceinline__ unsigned swz16(int r, int ch) {
    return (unsigned)(r * 32 + ((ch ^ ((r >> 2) & 1)) << 4));
}

// ---------------- GEMM1, fused convert + bf16-split, via tensor cores --------------
#define NCHUNK 32

__global__ __launch_bounds__(512) void gemm1_fused_kernel(
    const float* __restrict__ X, const float* __restrict__ b1)
{
    __shared__ __nv_bfloat16 sAh[2][128 * 16];
    __shared__ __nv_bfloat16 sAl[2][128 * 16];
    __shared__ __nv_bfloat16 sWh[2][256 * 16];
    __shared__ __nv_bfloat16 sWl[2][256 * 16];   // total 48KB

    const int tid  = threadIdx.x;
    const int lane = tid & 31;
    const int wid  = tid >> 5;
    const int wm   = wid & 3;
    const int wn   = wid >> 2;
    const int m0 = blockIdx.x * 128;

    const int ar  = tid >> 2;
    const int ac4 = (tid & 3) * 4;
    int arow = m0 + ar; if (arow > NNODES - 1) arow = NNODES - 1;
    const float* xsrc = X + (size_t)arow * FIN + ac4;
    const unsigned stsOff = swz16(ar, ac4 >> 3) + (ac4 & 4) * 2;

    const int wr  = tid >> 1;
    const int wch = tid & 1;
    const unsigned wOff = swz16(wr, wch);
    const __nv_bfloat16* whsrc = g_whT + (size_t)wr * FIN + wch * 8;
    const __nv_bfloat16* wlsrc = g_wlT + (size_t)wr * FIN + wch * 8;

    float acc[2][8][4];
    #pragma unroll
    for (int mf = 0; mf < 2; mf++)
        #pragma unroll
        for (int nf = 0; nf < 8; nf++)
            #pragma unroll
            for (int q = 0; q < 4; q++) acc[mf][nf][q] = 0.0f;

    float4 xcur = *(const float4*)xsrc;
    {
        cpasync16(smem_u32(sWh[0]) + wOff, whsrc);
        cpasync16(smem_u32(sWl[0]) + wOff, wlsrc);
        asm volatile("cp.async.commit_group;\n" ::);
    }

    for (int i = 0; i < NCHUNK; i++) {
        const int buf = i & 1;
        float4 xnext;
        if (i + 1 < NCHUNK) {
            xnext = *(const float4*)(xsrc + (i + 1) * 16);
            cpasync16(smem_u32(sWh[buf ^ 1]) + wOff, whsrc + (i + 1) * 16);
            cpasync16(smem_u32(sWl[buf ^ 1]) + wOff, wlsrc + (i + 1) * 16);
            asm volatile("cp.async.commit_group;\n" ::);
            asm volatile("cp.async.wait_group 1;\n" ::);
        } else {
            asm volatile("cp.async.wait_group 0;\n" ::);
        }

        {
            __nv_bfloat16 h0 = __float2bfloat16(xcur.x);
            __nv_bfloat16 h1 = __float2bfloat16(xcur.y);
            __nv_bfloat16 h2 = __float2bfloat16(xcur.z);
            __nv_bfloat16 h3 = __float2bfloat16(xcur.w);
            uint2 vh = make_uint2(pack_bf16x2(h0, h1), pack_bf16x2(h2, h3));
            __nv_bfloat16 l0 = __float2bfloat16(xcur.x - __bfloat162float(h0));
            __nv_bfloat16 l1 = __float2bfloat16(xcur.y - __bfloat162float(h1));
            __nv_bfloat16 l2 = __float2bfloat16(xcur.z - __bfloat162float(h2));
            __nv_bfloat16 l3 = __float2bfloat16(xcur.w - __bfloat162float(h3));
            uint2 vl = make_uint2(pack_bf16x2(l0, l1), pack_bf16x2(l2, l3));
            *(uint2*)((char*)sAh[buf] + stsOff) = vh;
            *(uint2*)((char*)sAl[buf] + stsOff) = vl;
        }
        __syncthreads();

        {
            const unsigned ahb = smem_u32(sAh[buf]);
            const unsigned alb = smem_u32(sAl[buf]);
            const unsigned whb = smem_u32(sWh[buf]);
            const unsigned wlb = smem_u32(sWl[buf]);

            unsigned fwh[8][2];
            #pragma unroll
            for (int np = 0; np < 4; np++) {
                int mat = lane >> 3, rr = lane & 7;
                int n  = wn * 64 + np * 16 + (mat >> 1) * 8 + rr;
                int ch = mat & 1;
                unsigned t[4];
                ldmatrix_x4(t, whb + swz16(n, ch));
                fwh[np * 2][0] = t[0];     fwh[np * 2][1] = t[1];
                fwh[np * 2 + 1][0] = t[2]; fwh[np * 2 + 1][1] = t[3];
            }
            unsigned fal[2][4];
            #pragma unroll
            for (int mf = 0; mf < 2; mf++) {
                int row = wm * 32 + mf * 16 + (lane & 15);
                ldmatrix_x4(fal[mf], alb + swz16(row, lane >> 4));
            }
            #pragma unroll
            for (int mf = 0; mf < 2; mf++)
                #pragma unroll
                for (int nf = 0; nf < 8; nf++)
                    mma_bf16(acc[mf][nf], fal[mf], fwh[nf]);

            unsigned fah[2][4];
            #pragma unroll
            for (int mf = 0; mf < 2; mf++) {
                int row = wm * 32 + mf * 16 + (lane & 15);
                ldmatrix_x4(fah[mf], ahb + swz16(row, lane >> 4));
            }
            #pragma unroll
            for (int mf = 0; mf < 2; mf++)
                #pragma unroll
                for (int nf = 0; nf < 8; nf++)
                    mma_bf16(acc[mf][nf], fah[mf], fwh[nf]);

            unsigned fwl[8][2];
            #pragma unroll
            for (int np = 0; np < 4; np++) {
                int mat = lane >> 3, rr = lane & 7;
                int n  = wn * 64 + np * 16 + (mat >> 1) * 8 + rr;
                int ch = mat & 1;
                unsigned t[4];
                ldmatrix_x4(t, wlb + swz16(n, ch));
                fwl[np * 2][0] = t[0];     fwl[np * 2][1] = t[1];
                fwl[np * 2 + 1][0] = t[2]; fwl[np * 2 + 1][1] = t[3];
            }
            #pragma unroll
            for (int mf = 0; mf < 2; mf++)
                #pragma unroll
                for (int nf = 0; nf < 8; nf++)
                    mma_bf16(acc[mf][nf], fah[mf], fwl[nf]);
        }
        __syncthreads();
        xcur = xnext;
    }

    const int g  = lane >> 2;
    const int c2 = (lane & 3) * 2;
    #pragma unroll
    for (int mf = 0; mf < 2; mf++) {
        #pragma unroll
        for (int nf = 0; nf < 8; nf++) {
            int n = wn * 64 + nf * 8 + c2;
            float bn0 = b1[n], bn1 = b1[n + 1];
            int m_lo = m0 + wm * 32 + mf * 16 + g;
            int m_hi = m_lo + 8;
            if (m_lo < NNODES) {
                float2 v = make_float2(fmaxf(acc[mf][nf][0] + bn0, 0.0f),
                                       fmaxf(acc[mf][nf][1] + bn1, 0.0f));
                *(float2*)&g_hid[(size_t)m_lo * HID + n] = v;
            }
            if (m_hi < NNODES) {
                float2 v = make_float2(fmaxf(acc[mf][nf][2] + bn0, 0.0f),
                                       fmaxf(acc[mf][nf][3] + bn1, 0.0f));
                *(float2*)&g_hid[(size_t)m_hi * HID + n] = v;
            }
        }
    }
}

// ---------------- GEMM2: h = hid @ W2 + b2, writes fp32 + fp16 copies -------------
__global__ __launch_bounds__(256) void gemm2_kernel(
    const float* __restrict__ W2, const float* __restrict__ b2)
{
    __shared__ float Hs[32][65];
    __shared__ float Ws[32][40];

    int tid = threadIdx.x;
    int m0 = blockIdx.x * 64;
    int tx = tid & 7;        // 8 -> 5 cols each
    int ty = tid >> 3;       // 32 -> 2 rows each

    float acc[2][5];
    #pragma unroll
    for (int r = 0; r < 2; r++)
        #pragma unroll
        for (int j = 0; j < 5; j++) acc[r][j] = 0.0f;

    for (int k0 = 0; k0 < HID; k0 += 32) {
        {
            int kk = tid & 31;
            int mb = tid >> 5;
            #pragma unroll
            for (int mi = 0; mi < 8; mi++) {
                int m = mi * 8 + mb;
                float v = 0.0f;
                if (m0 + m < NNODES)
                    v = g_hid[(size_t)(m0 + m) * HID + k0 + kk];
                Hs[kk][m] = v;
            }
        }
        #pragma unroll
        for (int l = 0; l < 5; l++) {
            int idx = tid + l * 256;
            int kr = idx / 40;
            int n = idx - kr * 40;
            Ws[kr][n] = W2[(size_t)(k0 + kr) * NC + n];
        }
        __syncthreads();

        #pragma unroll
        for (int k = 0; k < 32; k++) {
            float a0 = Hs[k][ty * 2];
            float a1 = Hs[k][ty * 2 + 1];
            #pragma unroll
            for (int j = 0; j < 5; j++) {
                float b = Ws[k][tx * 5 + j];
                acc[0][j] += a0 * b;
                acc[1][j] += a1 * b;
            }
        }
        __syncthreads();
    }

    #pragma unroll
    for (int r = 0; r < 2; r++) {
        int m = m0 + ty * 2 + r;
        if (m < NNODES) {
            #pragma unroll
            for (int j = 0; j < 5; j++) {
                int n = tx * 5 + j;
                float v = acc[r][j] + b2[n];
                g_h[(size_t)m * NC + n] = v;
                g_h16[(size_t)m * NC + n] = __float2half_rn(v);
            }
        }
    }
}

// ---------------- fp16 gather helper ----------------
__device__ __forceinline__ float4 ldz16(const __half* p) {
    uint2 raw = *(const uint2*)p;
    __half2 a = *(__half2*)&raw.x;
    __half2 b = *(__half2*)&raw.y;
    float2 fa = __half22float2(a), fb = __half22float2(b);
    return make_float4(fa.x, fa.y, fb.x, fb.y);
}

// ---------------- APPNP step (fp16 z): zout = 0.9*A_norm*zin + 0.1*h --------------
// warp per row; 3 edge sub-groups of 10 lanes, each lane owns 4 channels (8B fp16)
__global__ __launch_bounds__(256) void spmm16_kernel(int srcSel, int dstSel) {
    const __half* zin  = (srcSel == 0) ? g_h16 : (srcSel == 1 ? g_z16A : g_z16B);
    __half*       zout = (dstSel == 1) ? g_z16A : g_z16B;

    int w = (blockIdx.x * blockDim.x + threadIdx.x) >> 5;
    int lane = threadIdx.x & 31;
    if (w >= NNODES) return;
    int s = g_rowptr[w];
    int e = g_rowptr[w + 1];

    int sub = lane / 10;
    int cg  = lane - sub * 10;

    float4 acc = make_float4(0.f, 0.f, 0.f, 0.f);
    if (sub < 3) {
        for (int j = s + sub; j < e; j += 3) {
            int2 ed = __ldg(&g_edge[j]);
            float wt = __int_as_float(ed.y);
            float4 zv = ldz16(zin + (size_t)ed.x * NC + cg * 4);
            acc.x += wt * zv.x;
            acc.y += wt * zv.y;
            acc.z += wt * zv.z;
            acc.w += wt * zv.w;
        }
    }

    float tx1 = __shfl_down_sync(0xffffffff, acc.x, 10);
    float ty1 = __shfl_down_sync(0xffffffff, acc.y, 10);
    float tz1 = __shfl_down_sync(0xffffffff, acc.z, 10);
    float tw1 = __shfl_down_sync(0xffffffff, acc.w, 10);
    float tx2 = __shfl_down_sync(0xffffffff, acc.x, 20);
    float ty2 = __shfl_down_sync(0xffffffff, acc.y, 20);
    float tz2 = __shfl_down_sync(0xffffffff, acc.z, 20);
    float tw2 = __shfl_down_sync(0xffffffff, acc.w, 20);

    if (lane < 10) {
        acc.x += tx1 + tx2;
        acc.y += ty1 + ty2;
        acc.z += tz1 + tz2;
        acc.w += tw1 + tw2;

        float dv = g_dinv[w];
        float ws = dv * dv;
        float4 zr = ldz16(zin + (size_t)w * NC + cg * 4);
        acc.x += ws * zr.x;
        acc.y += ws * zr.y;
        acc.z += ws * zr.z;
        acc.w += ws * zr.w;

        float4 hr = *(const float4*)(g_h + (size_t)w * NC + cg * 4);
        float ox = (1.0f - ALPHA) * acc.x + ALPHA * hr.x;
        float oy = (1.0f - ALPHA) * acc.y + ALPHA * hr.y;
        float oz = (1.0f - ALPHA) * acc.z + ALPHA * hr.z;
        float ow = (1.0f - ALPHA) * acc.w + ALPHA * hr.w;
        __half2 q0 = __floats2half2_rn(ox, oy);
        __half2 q1 = __floats2half2_rn(oz, ow);
        uint2 packed = make_uint2(*(unsigned*)&q0, *(unsigned*)&q1);
        *(uint2*)(zout + (size_t)w * NC + cg * 4) = packed;
    }
}

// ---------------- final APPNP step fused with log_softmax -> out fp32 --------------
__global__ __launch_bounds__(256) void spmm_last_kernel(float* __restrict__ out) {
    const __half* zin = g_z16A;    // step 9 output

    int w = (blockIdx.x * blockDim.x + threadIdx.x) >> 5;
    int lane = threadIdx.x & 31;
    if (w >= NNODES) return;
    int s = g_rowptr[w];
    int e = g_rowptr[w + 1];

    int sub = lane / 10;
    int cg  = lane - sub * 10;

    float4 acc = make_float4(0.f, 0.f, 0.f, 0.f);
    if (sub < 3) {
        for (int j = s + sub; j < e; j += 3) {
            int2 ed = __ldg(&g_edge[j]);
            float wt = __int_as_float(ed.y);
            float4 zv = ldz16(zin + (size_t)ed.x * NC + cg * 4);
            acc.x += wt * zv.x;
            acc.y += wt * zv.y;
            acc.z += wt * zv.z;
            acc.w += wt * zv.w;
        }
    }

    float tx1 = __shfl_down_sync(0xffffffff, acc.x, 10);
    float ty1 = __shfl_down_sync(0xffffffff, acc.y, 10);
    float tz1 = __shfl_down_sync(0xffffffff, acc.z, 10);
    float tw1 = __shfl_down_sync(0xffffffff, acc.w, 10);
    float tx2 = __shfl_down_sync(0xffffffff, acc.x, 20);
    float ty2 = __shfl_down_sync(0xffffffff, acc.y, 20);
    float tz2 = __shfl_down_sync(0xffffffff, acc.z, 20);
    float tw2 = __shfl_down_sync(0xffffffff, acc.w, 20);

    float ox = 0.f, oy = 0.f, oz = 0.f, ow = 0.f;
    float mloc = -3.4e38f;
    if (lane < 10) {
        acc.x += tx1 + tx2;
        acc.y += ty1 + ty2;
        acc.z += tz1 + tz2;
        acc.w += tw1 + tw2;

        float dv = g_dinv[w];
        float ws = dv * dv;
        float4 zr = ldz16(zin + (size_t)w * NC + cg * 4);
        acc.x += ws * zr.x;
        acc.y += ws * zr.y;
        acc.z += ws * zr.z;
        acc.w += ws * zr.w;

        float4 hr = *(const float4*)(g_h + (size_t)w * NC + cg * 4);
        ox = (1.0f - ALPHA) * acc.x + ALPHA * hr.x;
        oy = (1.0f - ALPHA) * acc.y + ALPHA * hr.y;
        oz = (1.0f - ALPHA) * acc.z + ALPHA * hr.z;
        ow = (1.0f - ALPHA) * acc.w + ALPHA * hr.w;
        mloc = fmaxf(fmaxf(ox, oy), fmaxf(oz, ow));
    }

    // log_softmax over 40 values spread across lanes 0..9 (xor-reduce width 16;
    // lanes 10-15 contribute identity)
    #pragma unroll
    for (int off = 8; off > 0; off >>= 1)
        mloc = fmaxf(mloc, __shfl_xor_sync(0xffffffff, mloc, off, 16));

    float sloc = 0.0f;
    if (lane < 10)
        sloc = __expf(ox - mloc) + __expf(oy - mloc) + __expf(oz - mloc) + __expf(ow - mloc);
    #pragma unroll
    for (int off = 8; off > 0; off >>= 1)
        sloc += __shfl_xor_sync(0xffffffff, sloc, off, 16);

    if (lane < 10) {
        float lse = mloc + logf(sloc);
        float4 o = make_float4(ox - lse, oy - lse, oz - lse, ow - lse);
        *(float4*)(out + (size_t)w * NC + cg * 4) = o;
    }
}

// ---------------- launch ----------------
extern "C" void kernel_launch(void* const* d_in, const int* in_sizes, int n_in,
                              void* d_out, int out_size) {
    const float* x  = (const float*)d_in[0];
    const float* W1 = (const float*)d_in[1];
    const float* b1 = (const float*)d_in[2];
    const float* W2 = (const float*)d_in[3];
    const float* b2 = (const float*)d_in[4];
    const int*   ei = (const int*)d_in[5];
    float* out = (float*)d_out;
    int E = in_sizes[5] / 2;

    // side stream for graph preprocessing (independent of MLP until spmm)
    static cudaStream_t s2 = nullptr;
    static cudaEvent_t evFork = nullptr, evJoin = nullptr;
    if (s2 == nullptr) {
        cudaStreamCreateWithFlags(&s2, cudaStreamNonBlocking);
        cudaEventCreateWithFlags(&evFork, cudaEventDisableTiming);
        cudaEventCreateWithFlags(&evJoin, cudaEventDisableTiming);
    }

    cudaEventRecord(evFork, 0);
    cudaStreamWaitEvent(s2, evFork, 0);

    // --- side stream: graph preprocessing -> CSR + normalized weights ---
    zero_deg_kernel<<<(NNODES + 255) / 256, 256, 0, s2>>>();
    count_deg_kernel<<<(E + 255) / 256, 256, 0, s2>>>(ei, E);
    scan_kernel<<<1, 1024, 0, s2>>>(E);
    scatter_kernel<<<(E + 255) / 256, 256, 0, s2>>>(ei, E);
    cudaEventRecord(evJoin, s2);

    // --- main stream: MLP encoder (overlaps with preprocessing) ---
    convert_w_kernel<<<(FIN * HID + 255) / 256, 256>>>(W1);
    gemm1_fused_kernel<<<(NNODES + 127) / 128, 512>>>(x, b1);
    gemm2_kernel<<<(NNODES + 63) / 64, 256>>>(W2, b2);

    // join: spmm needs both g_h/g_h16 (main) and CSR (s2)
    cudaStreamWaitEvent(0, evJoin, 0);

    // steps 1..9 on fp16 z; step 10 fused with log_softmax
    int spmmGrid = (NNODES * 32 + 255) / 256;
    for (int i = 1; i <= KSTEPS - 1; i++) {
        int src = (i == 1) ? 0 : ((i & 1) ? 2 : 1);
        int dst = (i & 1) ? 1 : 2;
        spmm16_kernel<<<spmmGrid, 256>>>(src, dst);
    }
    spmm_last_kernel<<<spmmGrid, 256>>>(out);   // reads g_z16A (step-9 output)
}

// round 12
// speedup vs baseline: 2.2646x; 1.0524x over previous
#include <cuda_runtime.h>
#include <cuda_bf16.h>
#include <cuda_fp16.h>
#include <math.h>

#define NNODES 100000
#define FIN    512
#define HID    256
#define NC     40
#define KSTEPS 10
#define EMAX   3200000
#define ALPHA  0.1f

// ---------------- device scratch (no allocations allowed) ----------------
__device__ float g_hid[NNODES * HID];      // ~102 MB
__device__ float g_h  [NNODES * NC];       // 16 MB (fp32 h for injection)
__device__ __half g_h16 [NNODES * NC];     // 8 MB (fp16 h for step-1 gather)
__device__ __half g_z16A[NNODES * NC];     // 8 MB ping
__device__ __half g_z16B[NNODES * NC];     // 8 MB pong
__device__ float g_dinv[NNODES];
__device__ int   g_deg [NNODES];
__device__ int   g_rowptr[NNODES + 1];
__device__ int   g_fill[NNODES];
__device__ int2  g_edge[EMAX];             // (col, ew bits) packed

// fp16 W (transposed) for tensor-core gemm1 (x is fp16-split in-kernel)
__device__ __half g_wT[HID * FIN];         // [n][k], 0.26 MB

// ---------------- graph preprocessing ----------------
__global__ void zero_deg_kernel() {
    int i = blockIdx.x * blockDim.x + threadIdx.x;
    if (i < NNODES) g_deg[i] = 0;
}

__global__ void count_deg_kernel(const int* __restrict__ ei, int E) {
    int e = blockIdx.x * blockDim.x + threadIdx.x;
    if (e < E) atomicAdd(&g_deg[ei[e]], 1);
}

__global__ void scan_kernel(int E) {
    const int T = 1024;
    const int CH = (NNODES + T - 1) / T;
    int t = threadIdx.x;
    int beg = t * CH;
    int end = beg + CH; if (end > NNODES) end = NNODES;
    if (beg > NNODES) beg = NNODES;

    int sum = 0;
    for (int i = beg; i < end; i++) sum += g_deg[i];

    __shared__ int sh[1024];
    sh[t] = sum;
    __syncthreads();
    for (int off = 1; off < T; off <<= 1) {
        int v = (t >= off) ? sh[t - off] : 0;
        __syncthreads();
        sh[t] += v;
        __syncthreads();
    }
    int offset = sh[t] - sum;

    int running = offset;
    for (int i = beg; i < end; i++) {
        g_rowptr[i] = running;
        g_fill[i]   = running;
        g_dinv[i]   = rsqrtf((float)(g_deg[i] + 1));   // +1 self-loop
        running += g_deg[i];
    }
    if (t == T - 1) g_rowptr[NNODES] = sh[T - 1];
}

__global__ void scatter_kernel(const int* __restrict__ ei, int E) {
    int e = blockIdx.x * blockDim.x + threadIdx.x;
    if (e >= E) return;
    int r = ei[e];          // destination
    int c = ei[E + e];      // source
    int pos = atomicAdd(&g_fill[r], 1);
    g_edge[pos] = make_int2(c, __float_as_int(g_dinv[r] * g_dinv[c]));
}

// ---------------- W fp16 conversion (tiny: 0.26 MB) ----------------
__global__ void convert_w_kernel(const float* __restrict__ W1) {
    int i = blockIdx.x * blockDim.x + threadIdx.x;     // over FIN*HID
    if (i >= FIN * HID) return;
    int k = i / HID, n = i - k * HID;
    g_wT[n * FIN + k] = __float2half_rn(W1[i]);
}

// ---------------- helpers for mma path ----------------
__device__ __forceinline__ unsigned smem_u32(const void* p) {
    return (unsigned)__cvta_generic_to_shared(p);
}
__device__ __forceinline__ void cpasync16(unsigned saddr, const void* gaddr) {
    asm volatile("cp.async.cg.shared.global [%0], [%1], 16;\n" :: "r"(saddr), "l"(gaddr));
}
__device__ __forceinline__ void ldmatrix_x4(unsigned* r, unsigned addr) {
    asm volatile("ldmatrix.sync.aligned.m8n8.x4.shared.b16 {%0,%1,%2,%3}, [%4];\n"
                 : "=r"(r[0]), "=r"(r[1]), "=r"(r[2]), "=r"(r[3]) : "r"(addr));
}
__device__ __forceinline__ void mma_f16(float* d, const unsigned* a, const unsigned* b) {
    asm volatile("mma.sync.aligned.m16n8k16.row.col.f32.f16.f16.f32 "
                 "{%0,%1,%2,%3}, {%4,%5,%6,%7}, {%8,%9}, {%0,%1,%2,%3};\n"
                 : "+f"(d[0]), "+f"(d[1]), "+f"(d[2]), "+f"(d[3])
                 : "r"(a[0]), "r"(a[1]), "r"(a[2]), "r"(a[3]), "r"(b[0]), "r"(b[1]));
}
__device__ __forceinline__ unsigned pack_h16x2(__half lo, __half hi) {
    unsigned short ul = *(unsigned short*)&lo, uh = *(unsigned short*)&hi;
    return (unsigned)ul | ((unsigned)uh << 16);
}

// swizzled offset within [rows x 16] half tile (32B rows, 2 x 16B chunks).
__device__ __forceinline__ unsigned swz16(int r, int ch) {
    return (unsigned)(r * 32 + ((ch ^ ((r >> 2) & 1)) << 4));
}

// ---------------- GEMM1, fused convert + fp16 2-pass split, tensor cores -----------
// h1 = relu(x@W1 + b1) ~= relu(xh@w + xl@w + b1),  xh+xl = fp16 split of x, w fp16
// BM=128 BN=256(full HID) BK=16 (32 chunks x 2 passes), 512 threads (16 warps, 4m x 4n)
#define NCHUNK 32

__global__ __launch_bounds__(512) void gemm1_fused_kernel(
    const float* __restrict__ X, const float* __restrict__ b1)
{
    __shared__ __half sXh[2][128 * 16];   // 4KB each
    __shared__ __half sXl[2][128 * 16];   // 4KB each
    __shared__ __half sW [2][256 * 16];   // 8KB each  (total 32KB)

    const int tid  = threadIdx.x;
    const int lane = tid & 31;
    const int wid  = tid >> 5;
    const int wm   = wid & 3;     // 4 warps along M (32 rows each)
    const int wn   = wid >> 2;    // 4 warps along N (64 cols each)
    const int m0 = blockIdx.x * 128;

    // per-thread A coords: row = tid>>2, 4 k-floats at (tid&3)*4
    const int ar  = tid >> 2;
    const int ac4 = (tid & 3) * 4;
    int arow = m0 + ar; if (arow > NNODES - 1) arow = NNODES - 1;
    const float* xsrc = X + (size_t)arow * FIN + ac4;
    const unsigned stsOff = swz16(ar, ac4 >> 3) + (ac4 & 4) * 2;

    // W coords: row = tid>>1 (0..255), chunk = tid&1 (one 16B chunk per thread)
    const int wr  = tid >> 1;
    const int wch = tid & 1;
    const unsigned wOff = swz16(wr, wch);
    const __half* wsrc = g_wT + (size_t)wr * FIN + wch * 8;

    float acc[2][8][4];
    #pragma unroll
    for (int mf = 0; mf < 2; mf++)
        #pragma unroll
        for (int nf = 0; nf < 8; nf++)
            #pragma unroll
            for (int q = 0; q < 4; q++) acc[mf][nf][q] = 0.0f;

    // prologue: chunk 0
    float4 xcur = *(const float4*)xsrc;
    {
        cpasync16(smem_u32(sW[0]) + wOff, wsrc);
        asm volatile("cp.async.commit_group;\n" ::);
    }

    for (int i = 0; i < NCHUNK; i++) {
        const int buf = i & 1;
        float4 xnext;
        if (i + 1 < NCHUNK) {
            xnext = *(const float4*)(xsrc + (i + 1) * 16);
            cpasync16(smem_u32(sW[buf ^ 1]) + wOff, wsrc + (i + 1) * 16);
            asm volatile("cp.async.commit_group;\n" ::);
            asm volatile("cp.async.wait_group 1;\n" ::);
        } else {
            asm volatile("cp.async.wait_group 0;\n" ::);
        }

        // convert xcur -> xh/xl fp16 and store (8B each)
        {
            __half h0 = __float2half_rn(xcur.x);
            __half h1 = __float2half_rn(xcur.y);
            __half h2 = __float2half_rn(xcur.z);
            __half h3 = __float2half_rn(xcur.w);
            uint2 vh = make_uint2(pack_h16x2(h0, h1), pack_h16x2(h2, h3));
            __half l0 = __float2half_rn(xcur.x - __half2float(h0));
            __half l1 = __float2half_rn(xcur.y - __half2float(h1));
            __half l2 = __float2half_rn(xcur.z - __half2float(h2));
            __half l3 = __float2half_rn(xcur.w - __half2float(h3));
            uint2 vl = make_uint2(pack_h16x2(l0, l1), pack_h16x2(l2, l3));
            *(uint2*)((char*)sXh[buf] + stsOff) = vh;
            *(uint2*)((char*)sXl[buf] + stsOff) = vl;
        }
        __syncthreads();

        // compute chunk: 2 passes sharing the W fragments
        {
            const unsigned xhb = smem_u32(sXh[buf]);
            const unsigned xlb = smem_u32(sXl[buf]);
            const unsigned wb  = smem_u32(sW[buf]);

            unsigned fw[8][2];
            #pragma unroll
            for (int np = 0; np < 4; np++) {
                int mat = lane >> 3, rr = lane & 7;
                int n  = wn * 64 + np * 16 + (mat >> 1) * 8 + rr;
                int ch = mat & 1;
                unsigned t[4];
                ldmatrix_x4(t, wb + swz16(n, ch));
                fw[np * 2][0] = t[0];     fw[np * 2][1] = t[1];
                fw[np * 2 + 1][0] = t[2]; fw[np * 2 + 1][1] = t[3];
            }
            unsigned fxl[2][4];
            #pragma unroll
            for (int mf = 0; mf < 2; mf++) {
                int row = wm * 32 + mf * 16 + (lane & 15);
                ldmatrix_x4(fxl[mf], xlb + swz16(row, lane >> 4));
            }
            #pragma unroll
            for (int mf = 0; mf < 2; mf++)
                #pragma unroll
                for (int nf = 0; nf < 8; nf++)
                    mma_f16(acc[mf][nf], fxl[mf], fw[nf]);

            unsigned fxh[2][4];
            #pragma unroll
            for (int mf = 0; mf < 2; mf++) {
                int row = wm * 32 + mf * 16 + (lane & 15);
                ldmatrix_x4(fxh[mf], xhb + swz16(row, lane >> 4));
            }
            #pragma unroll
            for (int mf = 0; mf < 2; mf++)
                #pragma unroll
                for (int nf = 0; nf < 8; nf++)
                    mma_f16(acc[mf][nf], fxh[mf], fw[nf]);
        }
        __syncthreads();
        xcur = xnext;
    }

    // epilogue: relu(acc + bias) -> g_hid fp32
    const int g  = lane >> 2;
    const int c2 = (lane & 3) * 2;
    #pragma unroll
    for (int mf = 0; mf < 2; mf++) {
        #pragma unroll
        for (int nf = 0; nf < 8; nf++) {
            int n = wn * 64 + nf * 8 + c2;
            float bn0 = b1[n], bn1 = b1[n + 1];
            int m_lo = m0 + wm * 32 + mf * 16 + g;
            int m_hi = m_lo + 8;
            if (m_lo < NNODES) {
                float2 v = make_float2(fmaxf(acc[mf][nf][0] + bn0, 0.0f),
                                       fmaxf(acc[mf][nf][1] + bn1, 0.0f));
                *(float2*)&g_hid[(size_t)m_lo * HID + n] = v;
            }
            if (m_hi < NNODES) {
                float2 v = make_float2(fmaxf(acc[mf][nf][2] + bn0, 0.0f),
                                       fmaxf(acc[mf][nf][3] + bn1, 0.0f));
                *(float2*)&g_hid[(size_t)m_hi * HID + n] = v;
            }
        }
    }
}

// ---------------- GEMM2: h = hid @ W2 + b2, writes fp32 + fp16 copies -------------
__global__ __launch_bounds__(256) void gemm2_kernel(
    const float* __restrict__ W2, const float* __restrict__ b2)
{
    __shared__ float Hs[32][65];
    __shared__ float Ws[32][40];

    int tid = threadIdx.x;
    int m0 = blockIdx.x * 64;
    int tx = tid & 7;        // 8 -> 5 cols each
    int ty = tid >> 3;       // 32 -> 2 rows each

    float acc[2][5];
    #pragma unroll
    for (int r = 0; r < 2; r++)
        #pragma unroll
        for (int j = 0; j < 5; j++) acc[r][j] = 0.0f;

    for (int k0 = 0; k0 < HID; k0 += 32) {
        {
            int kk = tid & 31;
            int mb = tid >> 5;
            #pragma unroll
            for (int mi = 0; mi < 8; mi++) {
                int m = mi * 8 + mb;
                float v = 0.0f;
                if (m0 + m < NNODES)
                    v = g_hid[(size_t)(m0 + m) * HID + k0 + kk];
                Hs[kk][m] = v;
            }
        }
        #pragma unroll
        for (int l = 0; l < 5; l++) {
            int idx = tid + l * 256;
            int kr = idx / 40;
            int n = idx - kr * 40;
            Ws[kr][n] = W2[(size_t)(k0 + kr) * NC + n];
        }
        __syncthreads();

        #pragma unroll
        for (int k = 0; k < 32; k++) {
            float a0 = Hs[k][ty * 2];
            float a1 = Hs[k][ty * 2 + 1];
            #pragma unroll
            for (int j = 0; j < 5; j++) {
                float b = Ws[k][tx * 5 + j];
                acc[0][j] += a0 * b;
                acc[1][j] += a1 * b;
            }
        }
        __syncthreads();
    }

    #pragma unroll
    for (int r = 0; r < 2; r++) {
        int m = m0 + ty * 2 + r;
        if (m < NNODES) {
            #pragma unroll
            for (int j = 0; j < 5; j++) {
                int n = tx * 5 + j;
                float v = acc[r][j] + b2[n];
                g_h[(size_t)m * NC + n] = v;
                g_h16[(size_t)m * NC + n] = __float2half_rn(v);
            }
        }
    }
}

// ---------------- fp16 gather helper ----------------
__device__ __forceinline__ float4 ldz16(const __half* p) {
    uint2 raw = *(const uint2*)p;
    __half2 a = *(__half2*)&raw.x;
    __half2 b = *(__half2*)&raw.y;
    float2 fa = __half22float2(a), fb = __half22float2(b);
    return make_float4(fa.x, fa.y, fb.x, fb.y);
}

// ---------------- APPNP step (fp16 z): zout = 0.9*A_norm*zin + 0.1*h --------------
__global__ __launch_bounds__(256) void spmm16_kernel(int srcSel, int dstSel) {
    const __half* zin  = (srcSel == 0) ? g_h16 : (srcSel == 1 ? g_z16A : g_z16B);
    __half*       zout = (dstSel == 1) ? g_z16A : g_z16B;

    int w = (blockIdx.x * blockDim.x + threadIdx.x) >> 5;
    int lane = threadIdx.x & 31;
    if (w >= NNODES) return;
    int s = g_rowptr[w];
    int e = g_rowptr[w + 1];

    int sub = lane / 10;
    int cg  = lane - sub * 10;

    float4 acc = make_float4(0.f, 0.f, 0.f, 0.f);
    if (sub < 3) {
        #pragma unroll 4
        for (int j = s + sub; j < e; j += 3) {
            int2 ed = __ldg(&g_edge[j]);
            float wt = __int_as_float(ed.y);
            float4 zv = ldz16(zin + (size_t)ed.x * NC + cg * 4);
            acc.x += wt * zv.x;
            acc.y += wt * zv.y;
            acc.z += wt * zv.z;
            acc.w += wt * zv.w;
        }
    }

    float tx1 = __shfl_down_sync(0xffffffff, acc.x, 10);
    float ty1 = __shfl_down_sync(0xffffffff, acc.y, 10);
    float tz1 = __shfl_down_sync(0xffffffff, acc.z, 10);
    float tw1 = __shfl_down_sync(0xffffffff, acc.w, 10);
    float tx2 = __shfl_down_sync(0xffffffff, acc.x, 20);
    float ty2 = __shfl_down_sync(0xffffffff, acc.y, 20);
    float tz2 = __shfl_down_sync(0xffffffff, acc.z, 20);
    float tw2 = __shfl_down_sync(0xffffffff, acc.w, 20);

    if (lane < 10) {
        acc.x += tx1 + tx2;
        acc.y += ty1 + ty2;
        acc.z += tz1 + tz2;
        acc.w += tw1 + tw2;

        float dv = g_dinv[w];
        float ws = dv * dv;
        float4 zr = ldz16(zin + (size_t)w * NC + cg * 4);
        acc.x += ws * zr.x;
        acc.y += ws * zr.y;
        acc.z += ws * zr.z;
        acc.w += ws * zr.w;

        float4 hr = *(const float4*)(g_h + (size_t)w * NC + cg * 4);
        float ox = (1.0f - ALPHA) * acc.x + ALPHA * hr.x;
        float oy = (1.0f - ALPHA) * acc.y + ALPHA * hr.y;
        float oz = (1.0f - ALPHA) * acc.z + ALPHA * hr.z;
        float ow = (1.0f - ALPHA) * acc.w + ALPHA * hr.w;
        __half2 q0 = __floats2half2_rn(ox, oy);
        __half2 q1 = __floats2half2_rn(oz, ow);
        uint2 packed = make_uint2(*(unsigned*)&q0, *(unsigned*)&q1);
        *(uint2*)(zout + (size_t)w * NC + cg * 4) = packed;
    }
}

// ---------------- final APPNP step fused with log_softmax -> out fp32 --------------
__global__ __launch_bounds__(256) void spmm_last_kernel(float* __restrict__ out) {
    const __half* zin = g_z16A;    // step 9 output

    int w = (blockIdx.x * blockDim.x + threadIdx.x) >> 5;
    int lane = threadIdx.x & 31;
    if (w >= NNODES) return;
    int s = g_rowptr[w];
    int e = g_rowptr[w + 1];

    int sub = lane / 10;
    int cg  = lane - sub * 10;

    float4 acc = make_float4(0.f, 0.f, 0.f, 0.f);
    if (sub < 3) {
        #pragma unroll 4
        for (int j = s + sub; j < e; j += 3) {
            int2 ed = __ldg(&g_edge[j]);
            float wt = __int_as_float(ed.y);
            float4 zv = ldz16(zin + (size_t)ed.x * NC + cg * 4);
            acc.x += wt * zv.x;
            acc.y += wt * zv.y;
            acc.z += wt * zv.z;
            acc.w += wt * zv.w;
        }
    }

    float tx1 = __shfl_down_sync(0xffffffff, acc.x, 10);
    float ty1 = __shfl_down_sync(0xffffffff, acc.y, 10);
    float tz1 = __shfl_down_sync(0xffffffff, acc.z, 10);
    float tw1 = __shfl_down_sync(0xffffffff, acc.w, 10);
    float tx2 = __shfl_down_sync(0xffffffff, acc.x, 20);
    float ty2 = __shfl_down_sync(0xffffffff, acc.y, 20);
    float tz2 = __shfl_down_sync(0xffffffff, acc.z, 20);
    float tw2 = __shfl_down_sync(0xffffffff, acc.w, 20);

    float ox = 0.f, oy = 0.f, oz = 0.f, ow = 0.f;
    float mloc = -3.4e38f;
    if (lane < 10) {
        acc.x += tx1 + tx2;
        acc.y += ty1 + ty2;
        acc.z += tz1 + tz2;
        acc.w += tw1 + tw2;

        float dv = g_dinv[w];
        float ws = dv * dv;
        float4 zr = ldz16(zin + (size_t)w * NC + cg * 4);
        acc.x += ws * zr.x;
        acc.y += ws * zr.y;
        acc.z += ws * zr.z;
        acc.w += ws * zr.w;

        float4 hr = *(const float4*)(g_h + (size_t)w * NC + cg * 4);
        ox = (1.0f - ALPHA) * acc.x + ALPHA * hr.x;
        oy = (1.0f - ALPHA) * acc.y + ALPHA * hr.y;
        oz = (1.0f - ALPHA) * acc.z + ALPHA * hr.z;
        ow = (1.0f - ALPHA) * acc.w + ALPHA * hr.w;
        mloc = fmaxf(fmaxf(ox, oy), fmaxf(oz, ow));
    }

    #pragma unroll
    for (int off = 8; off > 0; off >>= 1)
        mloc = fmaxf(mloc, __shfl_xor_sync(0xffffffff, mloc, off, 16));

    float sloc = 0.0f;
    if (lane < 10)
        sloc = __expf(ox - mloc) + __expf(oy - mloc) + __expf(oz - mloc) + __expf(ow - mloc);
    #pragma unroll
    for (int off = 8; off > 0; off >>= 1)
        sloc += __shfl_xor_sync(0xffffffff, sloc, off, 16);

    if (lane < 10) {
        float lse = mloc + logf(sloc);
        float4 o = make_float4(ox - lse, oy - lse, oz - lse, ow - lse);
        *(float4*)(out + (size_t)w * NC + cg * 4) = o;
    }
}

// ---------------- launch ----------------
extern "C" void kernel_launch(void* const* d_in, const int* in_sizes, int n_in,
                              void* d_out, int out_size) {
    const float* x  = (const float*)d_in[0];
    const float* W1 = (const float*)d_in[1];
    const float* b1 = (const float*)d_in[2];
    const float* W2 = (const float*)d_in[3];
    const float* b2 = (const float*)d_in[4];
    const int*   ei = (const int*)d_in[5];
    float* out = (float*)d_out;
    int E = in_sizes[5] / 2;

    // side stream for graph preprocessing (independent of MLP until spmm)
    static cudaStream_t s2 = nullptr;
    static cudaEvent_t evFork = nullptr, evJoin = nullptr;
    if (s2 == nullptr) {
        cudaStreamCreateWithFlags(&s2, cudaStreamNonBlocking);
        cudaEventCreateWithFlags(&evFork, cudaEventDisableTiming);
        cudaEventCreateWithFlags(&evJoin, cudaEventDisableTiming);
    }

    cudaEventRecord(evFork, 0);
    cudaStreamWaitEvent(s2, evFork, 0);

    // --- side stream: graph preprocessing -> CSR + normalized weights ---
    zero_deg_kernel<<<(NNODES + 255) / 256, 256, 0, s2>>>();
    count_deg_kernel<<<(E + 255) / 256, 256, 0, s2>>>(ei, E);
    scan_kernel<<<1, 1024, 0, s2>>>(E);
    scatter_kernel<<<(E + 255) / 256, 256, 0, s2>>>(ei, E);
    cudaEventRecord(evJoin, s2);

    // --- main stream: MLP encoder (overlaps with preprocessing) ---
    convert_w_kernel<<<(FIN * HID + 255) / 256, 256>>>(W1);
    gemm1_fused_kernel<<<(NNODES + 127) / 128, 512>>>(x, b1);
    gemm2_kernel<<<(NNODES + 63) / 64, 256>>>(W2, b2);

    // join: spmm needs both g_h/g_h16 (main) and CSR (s2)
    cudaStreamWaitEvent(0, evJoin, 0);

    // steps 1..9 on fp16 z; step 10 fused with log_softmax
    int spmmGrid = (NNODES * 32 + 255) / 256;
    for (int i = 1; i <= KSTEPS - 1; i++) {
        int src = (i == 1) ? 0 : ((i & 1) ? 2 : 1);
        int dst = (i & 1) ? 1 : 2;
        spmm16_kernel<<<spmmGrid, 256>>>(src, dst);
    }
    spmm_last_kernel<<<spmmGrid, 256>>>(out);   // reads g_z16A (step-9 output)
}

// round 13
// speedup vs baseline: 2.6269x; 1.1600x over previous
#include <cuda_runtime.h>
#include <cuda_bf16.h>
#include <cuda_fp16.h>
#include <math.h>

#define NNODES 100000
#define FIN    512
#define HID    256
#define NC     40
#define KSTEPS 10
#define EMAX   3200000
#define ALPHA  0.1f

// ---------------- device scratch (no allocations allowed) ----------------
__device__ float g_hid[NNODES * HID];      // ~102 MB
__device__ float g_h  [NNODES * NC];       // 16 MB (fp32 h for injection)
__device__ __half g_h16 [NNODES * NC];     // 8 MB (fp16 h for step-1 gather)
__device__ __half g_z16A[NNODES * NC];     // 8 MB ping
__device__ __half g_z16B[NNODES * NC];     // 8 MB pong
__device__ float g_dinv[NNODES];
__device__ int   g_deg [NNODES];
__device__ int   g_rowptr[NNODES + 1];
__device__ int   g_fill[NNODES];
__device__ int2  g_edge[EMAX];             // (col, ew bits) packed

// fp16 W (transposed) for tensor-core gemm1 (x is fp16-converted in-kernel)
__device__ __half g_wT[HID * FIN];         // [n][k], 0.26 MB

// ---------------- graph preprocessing ----------------
__global__ void zero_deg_kernel() {
    int i = blockIdx.x * blockDim.x + threadIdx.x;
    if (i < NNODES) g_deg[i] = 0;
}

__global__ void count_deg_kernel(const int* __restrict__ ei, int E) {
    int e = blockIdx.x * blockDim.x + threadIdx.x;
    if (e < E) atomicAdd(&g_deg[ei[e]], 1);
}

__global__ void scan_kernel(int E) {
    const int T = 1024;
    const int CH = (NNODES + T - 1) / T;
    int t = threadIdx.x;
    int beg = t * CH;
    int end = beg + CH; if (end > NNODES) end = NNODES;
    if (beg > NNODES) beg = NNODES;

    int sum = 0;
    for (int i = beg; i < end; i++) sum += g_deg[i];

    __shared__ int sh[1024];
    sh[t] = sum;
    __syncthreads();
    for (int off = 1; off < T; off <<= 1) {
        int v = (t >= off) ? sh[t - off] : 0;
        __syncthreads();
        sh[t] += v;
        __syncthreads();
    }
    int offset = sh[t] - sum;

    int running = offset;
    for (int i = beg; i < end; i++) {
        g_rowptr[i] = running;
        g_fill[i]   = running;
        g_dinv[i]   = rsqrtf((float)(g_deg[i] + 1));   // +1 self-loop
        running += g_deg[i];
    }
    if (t == T - 1) g_rowptr[NNODES] = sh[T - 1];
}

__global__ void scatter_kernel(const int* __restrict__ ei, int E) {
    int e = blockIdx.x * blockDim.x + threadIdx.x;
    if (e >= E) return;
    int r = ei[e];          // destination
    int c = ei[E + e];      // source
    int pos = atomicAdd(&g_fill[r], 1);
    g_edge[pos] = make_int2(c, __float_as_int(g_dinv[r] * g_dinv[c]));
}

// ---------------- W fp16 conversion (tiny: 0.26 MB) ----------------
__global__ void convert_w_kernel(const float* __restrict__ W1) {
    int i = blockIdx.x * blockDim.x + threadIdx.x;     // over FIN*HID
    if (i >= FIN * HID) return;
    int k = i / HID, n = i - k * HID;
    g_wT[n * FIN + k] = __float2half_rn(W1[i]);
}

// ---------------- helpers for mma path ----------------
__device__ __forceinline__ unsigned smem_u32(const void* p) {
    return (unsigned)__cvta_generic_to_shared(p);
}
__device__ __forceinline__ void cpasync16(unsigned saddr, const void* gaddr) {
    asm volatile("cp.async.cg.shared.global [%0], [%1], 16;\n" :: "r"(saddr), "l"(gaddr));
}
__device__ __forceinline__ void ldmatrix_x4(unsigned* r, unsigned addr) {
    asm volatile("ldmatrix.sync.aligned.m8n8.x4.shared.b16 {%0,%1,%2,%3}, [%4];\n"
                 : "=r"(r[0]), "=r"(r[1]), "=r"(r[2]), "=r"(r[3]) : "r"(addr));
}
__device__ __forceinline__ void mma_f16(float* d, const unsigned* a, const unsigned* b) {
    asm volatile("mma.sync.aligned.m16n8k16.row.col.f32.f16.f16.f32 "
                 "{%0,%1,%2,%3}, {%4,%5,%6,%7}, {%8,%9}, {%0,%1,%2,%3};\n"
                 : "+f"(d[0]), "+f"(d[1]), "+f"(d[2]), "+f"(d[3])
                 : "r"(a[0]), "r"(a[1]), "r"(a[2]), "r"(a[3]), "r"(b[0]), "r"(b[1]));
}
__device__ __forceinline__ unsigned pack_h16x2(__half lo, __half hi) {
    unsigned short ul = *(unsigned short*)&lo, uh = *(unsigned short*)&hi;
    return (unsigned)ul | ((unsigned)uh << 16);
}

// swizzled offset within a [rows x 32] half tile (64B rows, 4 x 16B chunks).
// chunk ^= (r>>1)&3 -> conflict-free for all ldmatrix 8-row phases (verified R7).
__device__ __forceinline__ unsigned swz32(int r, int ch) {
    return (unsigned)(r * 64 + ((ch ^ ((r >> 1) & 3)) << 4));
}

// ---------------- GEMM1, fused fp32->fp16 convert, single-pass fp16 MMA ------------
// h1 = relu(x@W1 + b1) with x,W fp16, fp32 accum
// BM=128 BN=256(full HID) BK=32 (16 chunks), 512 threads (16 warps, 4m x 4n)
#define NCHUNK 16

__global__ __launch_bounds__(512) void gemm1_fused_kernel(
    const float* __restrict__ X, const float* __restrict__ b1)
{
    __shared__ __half sX[2][128 * 32];   // 8KB each
    __shared__ __half sW[2][256 * 32];   // 16KB each  (total 48KB)

    const int tid  = threadIdx.x;
    const int lane = tid & 31;
    const int wid  = tid >> 5;
    const int wm   = wid & 3;     // 4 warps along M (32 rows each)
    const int wn   = wid >> 2;    // 4 warps along N (64 cols each)
    const int m0 = blockIdx.x * 128;

    // per-thread X coords: row = tid>>2, 8 k-floats at (tid&3)*8 (two float4)
    const int ar  = tid >> 2;
    const int ac8 = (tid & 3) * 8;
    int arow = m0 + ar; if (arow > NNODES - 1) arow = NNODES - 1;
    const float* xsrc = X + (size_t)arow * FIN + ac8;
    const unsigned stsOff = swz32(ar, tid & 3);     // one 16B chunk of 8 halfs

    // W coords: 256 rows x 4 chunks = 1024 chunks, 2 per thread
    const unsigned wOff0 = swz32(tid >> 2, tid & 3);
    const unsigned wOff1 = swz32((tid + 512) >> 2, tid & 3);
    const __half* wsrc0 = g_wT + (size_t)(tid >> 2) * FIN + (tid & 3) * 8;
    const __half* wsrc1 = g_wT + (size_t)((tid + 512) >> 2) * FIN + (tid & 3) * 8;

    float acc[2][8][4];
    #pragma unroll
    for (int mf = 0; mf < 2; mf++)
        #pragma unroll
        for (int nf = 0; nf < 8; nf++)
            #pragma unroll
            for (int q = 0; q < 4; q++) acc[mf][nf][q] = 0.0f;

    // prologue: chunk 0
    float4 xc0 = *(const float4*)xsrc;
    float4 xc1 = *(const float4*)(xsrc + 4);
    {
        cpasync16(smem_u32(sW[0]) + wOff0, wsrc0);
        cpasync16(smem_u32(sW[0]) + wOff1, wsrc1);
        asm volatile("cp.async.commit_group;\n" ::);
    }

    for (int i = 0; i < NCHUNK; i++) {
        const int buf = i & 1;
        float4 xn0, xn1;
        if (i + 1 < NCHUNK) {
            xn0 = *(const float4*)(xsrc + (i + 1) * 32);
            xn1 = *(const float4*)(xsrc + (i + 1) * 32 + 4);
            cpasync16(smem_u32(sW[buf ^ 1]) + wOff0, wsrc0 + (i + 1) * 32);
            cpasync16(smem_u32(sW[buf ^ 1]) + wOff1, wsrc1 + (i + 1) * 32);
            asm volatile("cp.async.commit_group;\n" ::);
            asm volatile("cp.async.wait_group 1;\n" ::);
        } else {
            asm volatile("cp.async.wait_group 0;\n" ::);
        }

        // convert 8 fp32 -> 8 fp16, one 16B STS
        {
            uint4 v;
            v.x = pack_h16x2(__float2half_rn(xc0.x), __float2half_rn(xc0.y));
            v.y = pack_h16x2(__float2half_rn(xc0.z), __float2half_rn(xc0.w));
            v.z = pack_h16x2(__float2half_rn(xc1.x), __float2half_rn(xc1.y));
            v.w = pack_h16x2(__float2half_rn(xc1.z), __float2half_rn(xc1.w));
            *(uint4*)((char*)sX[buf] + stsOff) = v;
        }
        __syncthreads();

        // compute chunk: 2 k-halves of 16
        {
            const unsigned xb = smem_u32(sX[buf]);
            const unsigned wb = smem_u32(sW[buf]);
            #pragma unroll
            for (int ks = 0; ks < 2; ks++) {
                unsigned fx[2][4];
                #pragma unroll
                for (int mf = 0; mf < 2; mf++) {
                    int row = wm * 32 + mf * 16 + (lane & 15);
                    int ch  = ks * 2 + (lane >> 4);
                    ldmatrix_x4(fx[mf], xb + swz32(row, ch));
                }
                unsigned fw[8][2];
                #pragma unroll
                for (int np = 0; np < 4; np++) {
                    int mat = lane >> 3, rr = lane & 7;
                    int n  = wn * 64 + np * 16 + (mat >> 1) * 8 + rr;
                    int ch = ks * 2 + (mat & 1);
                    unsigned t[4];
                    ldmatrix_x4(t, wb + swz32(n, ch));
                    fw[np * 2][0] = t[0];     fw[np * 2][1] = t[1];
                    fw[np * 2 + 1][0] = t[2]; fw[np * 2 + 1][1] = t[3];
                }
                #pragma unroll
                for (int mf = 0; mf < 2; mf++)
                    #pragma unroll
                    for (int nf = 0; nf < 8; nf++)
                        mma_f16(acc[mf][nf], fx[mf], fw[nf]);
            }
        }
        __syncthreads();
        xc0 = xn0; xc1 = xn1;
    }

    // epilogue: relu(acc + bias) -> g_hid fp32
    const int g  = lane >> 2;
    const int c2 = (lane & 3) * 2;
    #pragma unroll
    for (int mf = 0; mf < 2; mf++) {
        #pragma unroll
        for (int nf = 0; nf < 8; nf++) {
            int n = wn * 64 + nf * 8 + c2;
            float bn0 = b1[n], bn1 = b1[n + 1];
            int m_lo = m0 + wm * 32 + mf * 16 + g;
            int m_hi = m_lo + 8;
            if (m_lo < NNODES) {
                float2 v = make_float2(fmaxf(acc[mf][nf][0] + bn0, 0.0f),
                                       fmaxf(acc[mf][nf][1] + bn1, 0.0f));
                *(float2*)&g_hid[(size_t)m_lo * HID + n] = v;
            }
            if (m_hi < NNODES) {
                float2 v = make_float2(fmaxf(acc[mf][nf][2] + bn0, 0.0f),
                                       fmaxf(acc[mf][nf][3] + bn1, 0.0f));
                *(float2*)&g_hid[(size_t)m_hi * HID + n] = v;
            }
        }
    }
}

// ---------------- GEMM2: h = hid @ W2 + b2, writes fp32 + fp16 copies -------------
__global__ __launch_bounds__(256) void gemm2_kernel(
    const float* __restrict__ W2, const float* __restrict__ b2)
{
    __shared__ float Hs[32][65];
    __shared__ float Ws[32][40];

    int tid = threadIdx.x;
    int m0 = blockIdx.x * 64;
    int tx = tid & 7;        // 8 -> 5 cols each
    int ty = tid >> 3;       // 32 -> 2 rows each

    float acc[2][5];
    #pragma unroll
    for (int r = 0; r < 2; r++)
        #pragma unroll
        for (int j = 0; j < 5; j++) acc[r][j] = 0.0f;

    for (int k0 = 0; k0 < HID; k0 += 32) {
        {
            int kk = tid & 31;
            int mb = tid >> 5;
            #pragma unroll
            for (int mi = 0; mi < 8; mi++) {
                int m = mi * 8 + mb;
                float v = 0.0f;
                if (m0 + m < NNODES)
                    v = g_hid[(size_t)(m0 + m) * HID + k0 + kk];
                Hs[kk][m] = v;
            }
        }
        #pragma unroll
        for (int l = 0; l < 5; l++) {
            int idx = tid + l * 256;
            int kr = idx / 40;
            int n = idx - kr * 40;
            Ws[kr][n] = W2[(size_t)(k0 + kr) * NC + n];
        }
        __syncthreads();

        #pragma unroll
        for (int k = 0; k < 32; k++) {
            float a0 = Hs[k][ty * 2];
            float a1 = Hs[k][ty * 2 + 1];
            #pragma unroll
            for (int j = 0; j < 5; j++) {
                float b = Ws[k][tx * 5 + j];
                acc[0][j] += a0 * b;
                acc[1][j] += a1 * b;
            }
        }
        __syncthreads();
    }

    #pragma unroll
    for (int r = 0; r < 2; r++) {
        int m = m0 + ty * 2 + r;
        if (m < NNODES) {
            #pragma unroll
            for (int j = 0; j < 5; j++) {
                int n = tx * 5 + j;
                float v = acc[r][j] + b2[n];
                g_h[(size_t)m * NC + n] = v;
                g_h16[(size_t)m * NC + n] = __float2half_rn(v);
            }
        }
    }
}

// ---------------- fp16 gather helper ----------------
__device__ __forceinline__ float4 ldz16(const __half* p) {
    uint2 raw = *(const uint2*)p;
    __half2 a = *(__half2*)&raw.x;
    __half2 b = *(__half2*)&raw.y;
    float2 fa = __half22float2(a), fb = __half22float2(b);
    return make_float4(fa.x, fa.y, fb.x, fb.y);
}

// ---------------- APPNP step (fp16 z): zout = 0.9*A_norm*zin + 0.1*h --------------
__global__ __launch_bounds__(256) void spmm16_kernel(int srcSel, int dstSel) {
    const __half* zin  = (srcSel == 0) ? g_h16 : (srcSel == 1 ? g_z16A : g_z16B);
    __half*       zout = (dstSel == 1) ? g_z16A : g_z16B;

    int w = (blockIdx.x * blockDim.x + threadIdx.x) >> 5;
    int lane = threadIdx.x & 31;
    if (w >= NNODES) return;
    int s = g_rowptr[w];
    int e = g_rowptr[w + 1];

    int sub = lane / 10;
    int cg  = lane - sub * 10;

    float4 acc = make_float4(0.f, 0.f, 0.f, 0.f);
    if (sub < 3) {
        #pragma unroll 4
        for (int j = s + sub; j < e; j += 3) {
            int2 ed = __ldg(&g_edge[j]);
            float wt = __int_as_float(ed.y);
            float4 zv = ldz16(zin + (size_t)ed.x * NC + cg * 4);
            acc.x += wt * zv.x;
            acc.y += wt * zv.y;
            acc.z += wt * zv.z;
            acc.w += wt * zv.w;
        }
    }

    float tx1 = __shfl_down_sync(0xffffffff, acc.x, 10);
    float ty1 = __shfl_down_sync(0xffffffff, acc.y, 10);
    float tz1 = __shfl_down_sync(0xffffffff, acc.z, 10);
    float tw1 = __shfl_down_sync(0xffffffff, acc.w, 10);
    float tx2 = __shfl_down_sync(0xffffffff, acc.x, 20);
    float ty2 = __shfl_down_sync(0xffffffff, acc.y, 20);
    float tz2 = __shfl_down_sync(0xffffffff, acc.z, 20);
    float tw2 = __shfl_down_sync(0xffffffff, acc.w, 20);

    if (lane < 10) {
        acc.x += tx1 + tx2;
        acc.y += ty1 + ty2;
        acc.z += tz1 + tz2;
        acc.w += tw1 + tw2;

        float dv = g_dinv[w];
        float ws = dv * dv;
        float4 zr = ldz16(zin + (size_t)w * NC + cg * 4);
        acc.x += ws * zr.x;
        acc.y += ws * zr.y;
        acc.z += ws * zr.z;
        acc.w += ws * zr.w;

        float4 hr = *(const float4*)(g_h + (size_t)w * NC + cg * 4);
        float ox = (1.0f - ALPHA) * acc.x + ALPHA * hr.x;
        float oy = (1.0f - ALPHA) * acc.y + ALPHA * hr.y;
        float oz = (1.0f - ALPHA) * acc.z + ALPHA * hr.z;
        float ow = (1.0f - ALPHA) * acc.w + ALPHA * hr.w;
        __half2 q0 = __floats2half2_rn(ox, oy);
        __half2 q1 = __floats2half2_rn(oz, ow);
        uint2 packed = make_uint2(*(unsigned*)&q0, *(unsigned*)&q1);
        *(uint2*)(zout + (size_t)w * NC + cg * 4) = packed;
    }
}

// ---------------- final APPNP step fused with log_softmax -> out fp32 --------------
__global__ __launch_bounds__(256) void spmm_last_kernel(float* __restrict__ out) {
    const __half* zin = g_z16A;    // step 9 output

    int w = (blockIdx.x * blockDim.x + threadIdx.x) >> 5;
    int lane = threadIdx.x & 31;
    if (w >= NNODES) return;
    int s = g_rowptr[w];
    int e = g_rowptr[w + 1];

    int sub = lane / 10;
    int cg  = lane - sub * 10;

    float4 acc = make_float4(0.f, 0.f, 0.f, 0.f);
    if (sub < 3) {
        #pragma unroll 4
        for (int j = s + sub; j < e; j += 3) {
            int2 ed = __ldg(&g_edge[j]);
            float wt = __int_as_float(ed.y);
            float4 zv = ldz16(zin + (size_t)ed.x * NC + cg * 4);
            acc.x += wt * zv.x;
            acc.y += wt * zv.y;
            acc.z += wt * zv.z;
            acc.w += wt * zv.w;
        }
    }

    float tx1 = __shfl_down_sync(0xffffffff, acc.x, 10);
    float ty1 = __shfl_down_sync(0xffffffff, acc.y, 10);
    float tz1 = __shfl_down_sync(0xffffffff, acc.z, 10);
    float tw1 = __shfl_down_sync(0xffffffff, acc.w, 10);
    float tx2 = __shfl_down_sync(0xffffffff, acc.x, 20);
    float ty2 = __shfl_down_sync(0xffffffff, acc.y, 20);
    float tz2 = __shfl_down_sync(0xffffffff, acc.z, 20);
    float tw2 = __shfl_down_sync(0xffffffff, acc.w, 20);

    float ox = 0.f, oy = 0.f, oz = 0.f, ow = 0.f;
    float mloc = -3.4e38f;
    if (lane < 10) {
        acc.x += tx1 + tx2;
        acc.y += ty1 + ty2;
        acc.z += tz1 + tz2;
        acc.w += tw1 + tw2;

        float dv = g_dinv[w];
        float ws = dv * dv;
        float4 zr = ldz16(zin + (size_t)w * NC + cg * 4);
        acc.x += ws * zr.x;
        acc.y += ws * zr.y;
        acc.z += ws * zr.z;
        acc.w += ws * zr.w;

        float4 hr = *(const float4*)(g_h + (size_t)w * NC + cg * 4);
        ox = (1.0f - ALPHA) * acc.x + ALPHA * hr.x;
        oy = (1.0f - ALPHA) * acc.y + ALPHA * hr.y;
        oz = (1.0f - ALPHA) * acc.z + ALPHA * hr.z;
        ow = (1.0f - ALPHA) * acc.w + ALPHA * hr.w;
        mloc = fmaxf(fmaxf(ox, oy), fmaxf(oz, ow));
    }

    #pragma unroll
    for (int off = 8; off > 0; off >>= 1)
        mloc = fmaxf(mloc, __shfl_xor_sync(0xffffffff, mloc, off, 16));

    float sloc = 0.0f;
    if (lane < 10)
        sloc = __expf(ox - mloc) + __expf(oy - mloc) + __expf(oz - mloc) + __expf(ow - mloc);
    #pragma unroll
    for (int off = 8; off > 0; off >>= 1)
        sloc += __shfl_xor_sync(0xffffffff, sloc, off, 16);

    if (lane < 10) {
        float lse = mloc + logf(sloc);
        float4 o = make_float4(ox - lse, oy - lse, oz - lse, ow - lse);
        *(float4*)(out + (size_t)w * NC + cg * 4) = o;
    }
}

// ---------------- launch ----------------
extern "C" void kernel_launch(void* const* d_in, const int* in_sizes, int n_in,
                              void* d_out, int out_size) {
    const float* x  = (const float*)d_in[0];
    const float* W1 = (const float*)d_in[1];
    const float* b1 = (const float*)d_in[2];
    const float* W2 = (const float*)d_in[3];
    const float* b2 = (const float*)d_in[4];
    const int*   ei = (const int*)d_in[5];
    float* out = (float*)d_out;
    int E = in_sizes[5] / 2;

    // side stream for graph preprocessing (independent of MLP until spmm)
    static cudaStream_t s2 = nullptr;
    static cudaEvent_t evFork = nullptr, evJoin = nullptr;
    if (s2 == nullptr) {
        cudaStreamCreateWithFlags(&s2, cudaStreamNonBlocking);
        cudaEventCreateWithFlags(&evFork, cudaEventDisableTiming);
        cudaEventCreateWithFlags(&evJoin, cudaEventDisableTiming);
    }

    cudaEventRecord(evFork, 0);
    cudaStreamWaitEvent(s2, evFork, 0);

    // --- side stream: graph preprocessing -> CSR + normalized weights ---
    zero_deg_kernel<<<(NNODES + 255) / 256, 256, 0, s2>>>();
    count_deg_kernel<<<(E + 255) / 256, 256, 0, s2>>>(ei, E);
    scan_kernel<<<1, 1024, 0, s2>>>(E);
    scatter_kernel<<<(E + 255) / 256, 256, 0, s2>>>(ei, E);
    cudaEventRecord(evJoin, s2);

    // --- main stream: MLP encoder (overlaps with preprocessing) ---
    convert_w_kernel<<<(FIN * HID + 255) / 256, 256>>>(W1);
    gemm1_fused_kernel<<<(NNODES + 127) / 128, 512>>>(x, b1);
    gemm2_kernel<<<(NNODES + 63) / 64, 256>>>(W2, b2);

    // join: spmm needs both g_h/g_h16 (main) and CSR (s2)
    cudaStreamWaitEvent(0, evJoin, 0);

    // steps 1..9 on fp16 z; step 10 fused with log_softmax
    int spmmGrid = (NNODES * 32 + 255) / 256;
    for (int i = 1; i <= KSTEPS - 1; i++) {
        int src = (i == 1) ? 0 : ((i & 1) ? 2 : 1);
        int dst = (i & 1) ? 1 : 2;
        spmm16_kernel<<<spmmGrid, 256>>>(src, dst);
    }
    spmm_last_kernel<<<spmmGrid, 256>>>(out);   // reads g_z16A (step-9 output)
}